// round 14
// baseline (speedup 1.0000x reference)
#include <cuda_runtime.h>
#include <cuda_bf16.h>
#include <math.h>

// ---------------- static scratch ----------------
__device__ __align__(256) float g_EMB[512*64*256];
__device__ __align__(256) float g_XA [512*64*512];
__device__ __align__(256) float g_XB [512*64*512];
__device__ __align__(256) float g_GT [512*64*2048];
__device__ __align__(256) float g_T0 [512*64*256];
__device__ __align__(256) float g_T1 [512*64*256];
__device__ __align__(256) float g_P0 [512*64*256];
__device__ __align__(256) float g_P1 [512*64*256];
__device__ __align__(256) float g_FU [64*774];
__device__ __align__(256) float g_S1 [64*512];
__device__ __align__(256) float g_S2 [64*256];
__device__ __align__(256) __nv_bfloat16 g_A3 [32768L*1536];
__device__ __align__(256) __nv_bfloat16 g_W3 [2048L*1536];
__device__ __align__(256) __nv_bfloat16 g_W3G[3L*256*768];

// ---------------- helpers ----------------
__device__ __forceinline__ float sigm(float x){ return 1.f/(1.f+__expf(-x)); }
__device__ __forceinline__ unsigned long long pk2f(float lo, float hi){
    unsigned long long u; asm("mov.b64 %0,{%1,%2};":"=l"(u):"f"(lo),"f"(hi)); return u;
}
__device__ __forceinline__ void fma2(unsigned long long&d,unsigned long long a,unsigned long long b){
    asm("fma.rn.f32x2 %0,%1,%2,%0;":"+l"(d):"l"(a),"l"(b));
}
__device__ __forceinline__ unsigned smem_u32(const void* p){
    unsigned a;
    asm("{ .reg .u64 t; cvta.to.shared.u64 t,%1; cvt.u32.u64 %0,t; }":"=r"(a):"l"(p));
    return a;
}
__device__ __forceinline__ void mbar_init(unsigned addr, unsigned cnt){
    asm volatile("mbarrier.init.shared.b64 [%0],%1;"::"r"(addr),"r"(cnt):"memory");
}
__device__ __forceinline__ void mbar_arrive_rank(unsigned local_addr, unsigned rank){
    asm volatile(
        "{ .reg .b32 ra;\n"
        "  mapa.shared::cluster.u32 ra,%0,%1;\n"
        "  mbarrier.arrive.release.cluster.shared::cluster.b64 _,[ra]; }"
        ::"r"(local_addr),"r"(rank):"memory");
}
__device__ __forceinline__ void mbar_wait(unsigned addr, unsigned parity){
    unsigned done;
    asm volatile(
        "{ .reg .pred p;\n"
        "  mbarrier.try_wait.parity.acquire.cluster.shared::cta.b64 p,[%1],%2;\n"
        "  selp.b32 %0,1,0,p; }"
        :"=r"(done):"r"(addr),"r"(parity):"memory");
    if(!done){
        asm volatile(
            "{ .reg .pred p;\n"
            "WL_%=:\n"
            "  mbarrier.try_wait.parity.acquire.cluster.shared::cta.b64 p,[%0],%1,0x989680;\n"
            "  @p bra.uni WD_%=;\n"
            "  bra.uni WL_%=;\n"
            "WD_%=: }"
            ::"r"(addr),"r"(parity):"memory");
    }
}
__device__ __forceinline__ void sts_cluster_f32(unsigned local_addr, unsigned rank, float v){
    asm volatile(
        "{ .reg .b32 ra;\n"
        "  mapa.shared::cluster.u32 ra,%0,%1;\n"
        "  st.shared::cluster.f32 [ra],%2; }"
        ::"r"(local_addr),"r"(rank),"f"(v):"memory");
}

// ---------------- embedding gather ----------------
__global__ void k_embed(const int* __restrict__ seq, const float* __restrict__ tab){
    int m = blockIdx.x; int s = m>>6, b = m&63;
    long tok = seq[b*512+s];
    const float4* src = (const float4*)(tab + tok*256);
    ((float4*)(g_EMB + (long)m*256))[threadIdx.x] = src[threadIdx.x];
}

// ---------------- bf16 split conversions ----------------
__global__ void k_splitA(const float* __restrict__ X, __nv_bfloat16* __restrict__ Y, int K){
    long idx = (long)blockIdx.x*256 + threadIdx.x;
    int kq = K>>2;
    long m = idx/kq; int k4 = (int)(idx - m*kq)*4;
    float4 v = *(const float4*)(X + m*K + k4);
    __nv_bfloat16 h0=__float2bfloat16(v.x), h1=__float2bfloat16(v.y);
    __nv_bfloat16 h2=__float2bfloat16(v.z), h3=__float2bfloat16(v.w);
    __nv_bfloat16 l0=__float2bfloat16(v.x-__bfloat162float(h0));
    __nv_bfloat16 l1=__float2bfloat16(v.y-__bfloat162float(h1));
    __nv_bfloat16 l2=__float2bfloat16(v.z-__bfloat162float(h2));
    __nv_bfloat16 l3=__float2bfloat16(v.w-__bfloat162float(h3));
    ushort4 hh = make_ushort4(__bfloat16_as_ushort(h0),__bfloat16_as_ushort(h1),
                              __bfloat16_as_ushort(h2),__bfloat16_as_ushort(h3));
    ushort4 ll = make_ushort4(__bfloat16_as_ushort(l0),__bfloat16_as_ushort(l1),
                              __bfloat16_as_ushort(l2),__bfloat16_as_ushort(l3));
    unsigned short* yp = (unsigned short*)(Y + m*3L*K + k4);
    *(ushort4*)yp = hh;
    *(ushort4*)(yp + K) = hh;
    *(ushort4*)(yp + 2*K) = ll;
}
__global__ void k_splitW(const float* __restrict__ X, __nv_bfloat16* __restrict__ Y, int K){
    long idx = (long)blockIdx.x*256 + threadIdx.x;
    int kq = K>>2;
    long m = idx/kq; int k4 = (int)(idx - m*kq)*4;
    float4 v = *(const float4*)(X + m*K + k4);
    __nv_bfloat16 h0=__float2bfloat16(v.x), h1=__float2bfloat16(v.y);
    __nv_bfloat16 h2=__float2bfloat16(v.z), h3=__float2bfloat16(v.w);
    __nv_bfloat16 l0=__float2bfloat16(v.x-__bfloat162float(h0));
    __nv_bfloat16 l1=__float2bfloat16(v.y-__bfloat162float(h1));
    __nv_bfloat16 l2=__float2bfloat16(v.z-__bfloat162float(h2));
    __nv_bfloat16 l3=__float2bfloat16(v.w-__bfloat162float(h3));
    ushort4 hh = make_ushort4(__bfloat16_as_ushort(h0),__bfloat16_as_ushort(h1),
                              __bfloat16_as_ushort(h2),__bfloat16_as_ushort(h3));
    ushort4 ll = make_ushort4(__bfloat16_as_ushort(l0),__bfloat16_as_ushort(l1),
                              __bfloat16_as_ushort(l2),__bfloat16_as_ushort(l3));
    unsigned short* yp = (unsigned short*)(Y + m*3L*K + k4);
    *(ushort4*)yp = hh;
    *(ushort4*)(yp + K) = ll;
    *(ushort4*)(yp + 2*K) = hh;
}

// ---------------- tensor-core GEMM (unchanged) ----------------
#define SPAD 72
__global__ void __launch_bounds__(256,2) k_mma(const __nv_bfloat16* __restrict__ A,
        const __nv_bfloat16* __restrict__ W, const float* __restrict__ bias,
        float* __restrict__ C, int Ks, int N){
    __shared__ __align__(16) __nv_bfloat16 As[128*SPAD];
    __shared__ __align__(16) __nv_bfloat16 Bs[128*SPAD];
    int tid = threadIdx.x;
    int m0 = blockIdx.y*128, n0 = blockIdx.x*128;
    int warp = tid>>5, lane = tid&31;
    int wm = (warp>>1)*32, wn = (warp&1)*64;
    int gid = lane>>2, tig = lane&3;
    float acc[2][8][4];
#pragma unroll
    for(int i=0;i<2;i++)
#pragma unroll
        for(int j=0;j<8;j++){ acc[i][j][0]=0.f; acc[i][j][1]=0.f; acc[i][j][2]=0.f; acc[i][j][3]=0.f; }
    for(int kt=0; kt<Ks; kt+=64){
#pragma unroll
        for(int i=0;i<4;i++){
            int idx = i*256 + tid;
            int r = idx>>3, c = (idx&7)*8;
            *(float4*)&As[r*SPAD + c] = *(const float4*)(A + (long)(m0+r)*Ks + kt + c);
            *(float4*)&Bs[r*SPAD + c] = *(const float4*)(W + (long)(n0+r)*Ks + kt + c);
        }
        __syncthreads();
#pragma unroll
        for(int kk=0;kk<4;kk++){
            unsigned a[2][4];
#pragma unroll
            for(int mt=0;mt<2;mt++){
                const __nv_bfloat16* ab = &As[(wm+mt*16+gid)*SPAD + kk*16 + tig*2];
                a[mt][0] = *(const unsigned*)ab;
                a[mt][1] = *(const unsigned*)(ab + 8*SPAD);
                a[mt][2] = *(const unsigned*)(ab + 8);
                a[mt][3] = *(const unsigned*)(ab + 8*SPAD + 8);
            }
#pragma unroll
            for(int nt=0;nt<8;nt++){
                const __nv_bfloat16* bb = &Bs[(wn+nt*8+gid)*SPAD + kk*16 + tig*2];
                unsigned b0 = *(const unsigned*)bb;
                unsigned b1 = *(const unsigned*)(bb + 8);
#pragma unroll
                for(int mt=0;mt<2;mt++){
                    asm volatile(
                        "mma.sync.aligned.m16n8k16.row.col.f32.bf16.bf16.f32 "
                        "{%0,%1,%2,%3},{%4,%5,%6,%7},{%8,%9},{%0,%1,%2,%3};\n"
                        : "+f"(acc[mt][nt][0]), "+f"(acc[mt][nt][1]),
                          "+f"(acc[mt][nt][2]), "+f"(acc[mt][nt][3])
                        : "r"(a[mt][0]), "r"(a[mt][1]), "r"(a[mt][2]), "r"(a[mt][3]),
                          "r"(b0), "r"(b1));
                }
            }
        }
        __syncthreads();
    }
#pragma unroll
    for(int mt=0;mt<2;mt++){
#pragma unroll
        for(int nt=0;nt<8;nt++){
            int row = m0 + wm + mt*16 + gid;
            int col = n0 + wn + nt*8 + tig*2;
            float b0v = bias[col], b1v = bias[col+1];
            *(float2*)&C[(long)row*N + col] =
                make_float2(acc[mt][nt][0]+b0v, acc[mt][nt][1]+b1v);
            *(float2*)&C[(long)(row+8)*N + col] =
                make_float2(acc[mt][nt][2]+b0v, acc[mt][nt][3]+b1v);
        }
    }
}

// ---------------- persistent LSTM: DSMEM cluster exchange -------------------
// 128 CTAs = dir(2) x bg(8 of 8 batch) x cluster(8 CTAs of 32 units).
// h exchanged via st.shared::cluster into peers' double-buffered smem;
// sync via per-buffer mbarrier (8 producer arrivals, release/acquire cluster).
#define PSP 10

__global__ void __launch_bounds__(256,1) __cluster_dims__(8,1,1)
k_lstm(const float* __restrict__ gates, const float* __restrict__ WhhA,
       const float* __restrict__ WhhB, float* __restrict__ out){
    __shared__ float hbuf[2][2048];          // [slot][256k][8b]
    __shared__ float ps[2*128*PSP];          // [2q][128r][PSP]
    __shared__ __align__(8) unsigned long long mbar[2];
    int tid = threadIdx.x, bid = blockIdx.x;
    int dir = bid>>6, bg = (bid>>3)&7, hb = bid&7;
    int hu0 = hb*32, b0 = bg*8;
    const float* Whh = dir ? WhhB : WhhA;
    int r = tid&127, q = tid>>7;             // row 0..127, k-half
    int gate = r>>5, ru = r&31;
    float4 wreg[32];
    {
        const float* wsrc = Whh + (long)(gate*256+hu0+ru)*256 + q*128;
#pragma unroll
        for(int j=0;j<32;j++) wreg[j] = *(const float4*)(wsrc + j*4);
    }
    int cu = tid>>3, cb = tid&7;             // combine: 32 units x 8 batch
    unsigned mb0 = smem_u32(&mbar[0]), mb1 = smem_u32(&mbar[1]);
    if(tid<2) mbar_init(tid?mb1:mb0, 8);
    for(int i=tid;i<2048;i+=256) hbuf[0][i]=0.f;   // h(0)=0 (own copy)
    __syncthreads();
    asm volatile("barrier.cluster.arrive.aligned;":::"memory");
    asm volatile("barrier.cluster.wait.aligned;":::"memory");
    float c = 0.f;
    int ph0 = 0, ph1 = 0;
    unsigned hst_local[2];
    hst_local[0] = smem_u32(&hbuf[0][(hu0+cu)*8+cb]);
    hst_local[1] = smem_u32(&hbuf[1][(hu0+cu)*8+cb]);
    for(int si=0; si<512; si++){
        int s = dir ? 511-si : si;
        int slot = si&1;
        // gate prefetch (overlaps wait)
        long gb = ((long)s*64 + b0+cb)*2048 + dir*1024 + hu0 + cu;
        float xi=__ldg(gates+gb),     xf=__ldg(gates+gb+256);
        float xg=__ldg(gates+gb+512), xo=__ldg(gates+gb+768);
        if(si){
            if(slot==0){ mbar_wait(mb0, ph0); ph0^=1; }
            else       { mbar_wait(mb1, ph1); ph1^=1; }
        }
        // dot: row r (gate*32+ru), k-half q, 8 batches
        const float* hq = &hbuf[slot][q*1024];
        unsigned long long a0=0,a1=0,a2=0,a3=0;
#pragma unroll
        for(int j=0;j<32;j++){
            float4 w4 = wreg[j];
            const ulonglong2* hp = (const ulonglong2*)(hq + j*32);
            ulonglong2 k0a=hp[0],k0b=hp[1],k1a=hp[2],k1b=hp[3];
            ulonglong2 k2a=hp[4],k2b=hp[5],k3a=hp[6],k3b=hp[7];
            unsigned long long w;
            w=pk2f(w4.x,w4.x); fma2(a0,w,k0a.x);fma2(a1,w,k0a.y);fma2(a2,w,k0b.x);fma2(a3,w,k0b.y);
            w=pk2f(w4.y,w4.y); fma2(a0,w,k1a.x);fma2(a1,w,k1a.y);fma2(a2,w,k1b.x);fma2(a3,w,k1b.y);
            w=pk2f(w4.z,w4.z); fma2(a0,w,k2a.x);fma2(a1,w,k2a.y);fma2(a2,w,k2b.x);fma2(a3,w,k2b.y);
            w=pk2f(w4.w,w4.w); fma2(a0,w,k3a.x);fma2(a1,w,k3a.y);fma2(a2,w,k3b.x);fma2(a3,w,k3b.y);
        }
        {
            unsigned long long* pr = (unsigned long long*)&ps[(q*128+r)*PSP];
            pr[0]=a0; pr[1]=a1; pr[2]=a2; pr[3]=a3;
        }
        __syncthreads();
        // combine (all 256 threads: unit cu, batch cb)
        float gi = ps[((0*32+cu))*PSP+cb] + ps[(128+0*32+cu)*PSP+cb] + xi;
        float gf = ps[((1*32+cu))*PSP+cb] + ps[(128+1*32+cu)*PSP+cb] + xf;
        float gg = ps[((2*32+cu))*PSP+cb] + ps[(128+2*32+cu)*PSP+cb] + xg;
        float go = ps[((3*32+cu))*PSP+cb] + ps[(128+3*32+cu)*PSP+cb] + xo;
        c = sigm(gf)*c + sigm(gi)*tanhf(gg);
        float h = sigm(go)*tanhf(c);
        // broadcast h into all 8 cluster CTAs' next-slot buffer
        {
            unsigned la = hst_local[1-slot];
#pragma unroll
            for(int p=0;p<8;p++) sts_cluster_f32(la, p, h);
        }
        out[((long)s*64 + b0+cb)*512 + dir*256 + hu0+cu] = h;
        __syncthreads();
        if(tid<8) mbar_arrive_rank(slot ? mb0 : mb1, tid);
    }
    asm volatile("barrier.cluster.arrive.aligned;":::"memory");
    asm volatile("barrier.cluster.wait.aligned;":::"memory");
}

// ---------------- GCN banded adjacency ----------------
__global__ void k_band(const float* __restrict__ x, const float* __restrict__ mask,
                       float* __restrict__ o){
    int m = blockIdx.x; int s=m>>6, b=m&63;
    float mm = mask[b*512+s];
    float mn = (s<511)? mask[b*512+s+1] : 0.f;
    float mp = (s>0)?   mask[b*512+s-1] : 0.f;
    float rs = mm*(mp+mn)+1e-8f;
    float cn = mm*mn/rs, cp = mm*mp/rs;
    int t = threadIdx.x;
    float4 vn = (s<511)? ((const float4*)(x+((long)m+64)*256))[t] : make_float4(0,0,0,0);
    float4 vp = (s>0)?   ((const float4*)(x+((long)m-64)*256))[t] : make_float4(0,0,0,0);
    float4 r; r.x=cn*vn.x+cp*vp.x; r.y=cn*vn.y+cp*vp.y;
    r.z=cn*vn.z+cp*vp.z; r.w=cn*vn.w+cp*vp.w;
    ((float4*)(o+(long)m*256))[t]=r;
}

// ---------------- residual + LayerNorm + ReLU ----------------
__global__ void k_ln(const float* __restrict__ go, const float* __restrict__ xin,
                     const float* __restrict__ gamma, const float* __restrict__ beta,
                     float* __restrict__ o){
    __shared__ float rs1[8], rs2[8];
    long m = blockIdx.x; int t = threadIdx.x;
    float v = go[m*256+t] + xin[m*256+t];
    float s1=v, s2=v*v;
#pragma unroll
    for(int w=16;w;w>>=1){ s1+=__shfl_xor_sync(~0u,s1,w); s2+=__shfl_xor_sync(~0u,s2,w); }
    if((t&31)==0){ rs1[t>>5]=s1; rs2[t>>5]=s2; }
    __syncthreads();
    float S1=0,S2=0;
#pragma unroll
    for(int i=0;i<8;i++){ S1+=rs1[i]; S2+=rs2[i]; }
    float mu=S1*(1.f/256.f), var=S2*(1.f/256.f)-mu*mu;
    float inv=rsqrtf(var+1e-5f);
    float y=(v-mu)*inv*gamma[t]+beta[t];
    o[m*256+t]=fmaxf(y,0.f);
}

// ---------------- masked mean pooling + fuse ----------------
__global__ void k_pool(const float* __restrict__ lstm, const float* __restrict__ gcn,
                       const float* __restrict__ mask, const float* __restrict__ aux){
    int b = blockIdx.x, t = threadIdx.x;
    float dn=0.f;
    for(int s=0;s<512;s++) dn += mask[b*512+s];
    dn = fmaxf(dn,1e-8f);
    float acc=0.f;
    for(int s=0;s<512;s++) acc += lstm[((long)s*64+b)*512+t]*mask[b*512+s];
    g_FU[b*774+t]=acc/dn;
    if(t<256){
        float a2=0.f;
        for(int s=0;s<512;s++) a2 += gcn[((long)s*64+b)*256+t]*mask[b*512+s];
        g_FU[b*774+512+t]=a2/dn;
    }
    if(t<6) g_FU[b*774+768+t]=aux[b*6+t];
}

// ---------------- small FC ----------------
__global__ void k_fc(const float* __restrict__ in, const float* __restrict__ W,
                     const float* __restrict__ bias, float* __restrict__ o,
                     int K, int N, int relu){
    int idx = blockIdx.x*blockDim.x + threadIdx.x;
    if(idx >= 64*N) return;
    int b = idx/N, n = idx%N;
    const float* ip = in + (long)b*K;
    const float* wp = W + (long)n*K;
    float a=0.f;
    for(int k=0;k<K;k++) a += ip[k]*wp[k];
    a += bias[n];
    o[idx] = relu ? fmaxf(a,0.f) : a;
}

// ---------------- launch ----------------
extern "C" void kernel_launch(void* const* d_in, const int* in_sizes, int n_in,
                              void* d_out, int out_size){
    const int*   seq  = (const int*)  d_in[0];
    const float* mask = (const float*)d_in[1];
    const float* aux  = (const float*)d_in[2];
    const float* emb  = (const float*)d_in[3];
    const float* Wih0 = (const float*)d_in[4];
    const float* Whh0 = (const float*)d_in[5];
    const float* b0   = (const float*)d_in[6];
    const float* WihL = (const float*)d_in[7];
    const float* WhhL = (const float*)d_in[8];
    const float* bLp  = (const float*)d_in[9];
    const float* gW   = (const float*)d_in[10];
    const float* gb   = (const float*)d_in[11];
    const float* gga  = (const float*)d_in[12];
    const float* gbe  = (const float*)d_in[13];
    const float* f1W  = (const float*)d_in[14];
    const float* f1b  = (const float*)d_in[15];
    const float* f2W  = (const float*)d_in[16];
    const float* f2b  = (const float*)d_in[17];
    const float* h0W  = (const float*)d_in[18];
    const float* h0b  = (const float*)d_in[19];
    const float* h1W  = (const float*)d_in[20];
    const float* h1b  = (const float*)d_in[21];
    float* out = (float*)d_out;

    float *pEMB,*pXA,*pXB,*pGT,*pT0,*pT1,*pP0,*pP1,*pFU,*pS1,*pS2;
    __nv_bfloat16 *pA3,*pW3,*pW3G;
    cudaGetSymbolAddress((void**)&pEMB,g_EMB);
    cudaGetSymbolAddress((void**)&pXA, g_XA);
    cudaGetSymbolAddress((void**)&pXB, g_XB);
    cudaGetSymbolAddress((void**)&pGT, g_GT);
    cudaGetSymbolAddress((void**)&pT0, g_T0);
    cudaGetSymbolAddress((void**)&pT1, g_T1);
    cudaGetSymbolAddress((void**)&pP0, g_P0);
    cudaGetSymbolAddress((void**)&pP1, g_P1);
    cudaGetSymbolAddress((void**)&pFU, g_FU);
    cudaGetSymbolAddress((void**)&pS1, g_S1);
    cudaGetSymbolAddress((void**)&pS2, g_S2);
    cudaGetSymbolAddress((void**)&pA3, g_A3);
    cudaGetSymbolAddress((void**)&pW3, g_W3);
    cudaGetSymbolAddress((void**)&pW3G,g_W3G);

    k_embed<<<32768,64>>>(seq, emb);                       // 0
    k_splitW<<<512,256>>>(Wih0, pW3, 256);                 // 1
    k_splitA<<<8192,256>>>(pEMB, pA3, 256);                // 2
    {   dim3 gg(2048/128, 32768/128);
        k_mma<<<gg,256>>>(pA3, pW3, b0, pGT, 768, 2048);   // 3
    }
    float* lo = pXA;
    k_lstm<<<128,256>>>(pGT, Whh0, Whh0 + 1024*256, lo);   // 4
    const float* inp = lo;
    for(int l=1;l<5;l++){
        const float* wih = WihL + (long)(l-1)*2*1024*512;
        const float* whh = WhhL + (long)(l-1)*2*1024*256;
        const float* bb  = bLp  + (long)(l-1)*2*1024;
        k_splitA<<<16384,256>>>(inp, pA3, 512);
        k_splitW<<<1024,256>>>(wih, pW3, 512);
        dim3 gg(2048/128, 32768/128);
        k_mma<<<gg,256>>>(pA3, pW3, bb, pGT, 1536, 2048);
        lo = (l&1) ? pXB : pXA;
        k_lstm<<<128,256>>>(pGT, whh, whh + 1024*256, lo);
        inp = lo;
    }
    const float* lstmOut = lo;

    k_splitW<<<64,256>>>(gW,             pW3G,            256);
    k_splitW<<<64,256>>>(gW + 256*256,   pW3G + 196608,   256);
    k_splitW<<<64,256>>>(gW + 2*256*256, pW3G + 2*196608, 256);

    const float* gin = pEMB;
    float* gout = pP0;
    for(int i=0;i<3;i++){
        k_band<<<32768,64>>>(gin, mask, pT0);
        k_splitA<<<8192,256>>>(pT0, pA3, 256);
        dim3 gg(256/128, 32768/128);
        k_mma<<<gg,256>>>(pA3, pW3G + (long)i*196608, gb + i*256, pT1, 768, 256);
        gout = (i&1) ? pP1 : pP0;
        k_ln<<<32768,256>>>(pT1, gin, gga + i*256, gbe + i*256, gout);
        gin = gout;
    }

    k_pool<<<64,512>>>(lstmOut, gout, mask, aux);
    k_fc<<<(64*512+255)/256,256>>>(pFU, f1W, f1b, pS1, 774, 512, 1);
    k_fc<<<(64*256+255)/256,256>>>(pS1, f2W, f2b, pS2, 512, 256, 1);
    k_fc<<<(64*10+255)/256,256>>>(pS2, h0W, h0b, out,      256, 10, 0);
    k_fc<<<(64*5 +255)/256,256>>>(pS2, h1W, h1b, out+640, 256,  5, 0);
}

// round 15
// speedup vs baseline: 1.2607x; 1.2607x over previous
#include <cuda_runtime.h>
#include <cuda_bf16.h>
#include <math.h>

// ---------------- static scratch ----------------
__device__ __align__(256) float g_EMB[512*64*256];
__device__ __align__(256) float g_XA [512*64*512];
__device__ __align__(256) float g_XB [512*64*512];
__device__ __align__(256) float g_GT [512*64*2048];
__device__ __align__(256) float g_T0 [512*64*256];
__device__ __align__(256) float g_T1 [512*64*256];
__device__ __align__(256) float g_P0 [512*64*256];
__device__ __align__(256) float g_P1 [512*64*256];
__device__ __align__(256) float g_H  [2*2*8*256*8];  // [pp][dir][bg][k][8b]
__device__ __align__(256) float g_FU [64*774];
__device__ __align__(256) float g_S1 [64*512];
__device__ __align__(256) float g_S2 [64*256];
__device__ __align__(256) __nv_bfloat16 g_A3 [32768L*1536];
__device__ __align__(256) __nv_bfloat16 g_W3 [2048L*1536];
__device__ __align__(256) __nv_bfloat16 g_W3G[3L*256*768];
__device__ unsigned g_barG[512];                     // 16 counters, 128B apart

// ---------------- helpers ----------------
__device__ __forceinline__ float sigm(float x){ return 1.f/(1.f+__expf(-x)); }
__device__ __forceinline__ unsigned long long pk2f(float lo, float hi){
    unsigned long long u; asm("mov.b64 %0,{%1,%2};":"=l"(u):"f"(lo),"f"(hi)); return u;
}
__device__ __forceinline__ void fma2(unsigned long long&d,unsigned long long a,unsigned long long b){
    asm("fma.rn.f32x2 %0,%1,%2,%0;":"+l"(d):"l"(a),"l"(b));
}
__device__ __forceinline__ void bar_arrive(unsigned* c){
    asm volatile("red.release.gpu.global.add.u32 [%0],1;"::"l"(c):"memory");
}
__device__ __forceinline__ void bar_poll(unsigned* c, unsigned tgt){
    unsigned v;
    while(1){
        asm volatile("ld.acquire.gpu.global.u32 %0,[%1];":"=r"(v):"l"(c):"memory");
        if(v>=tgt) break;
        __nanosleep(20);
    }
}
__device__ __forceinline__ void cpasync16(float* dst_smem, const float* src){
    unsigned d = (unsigned)__cvta_generic_to_shared(dst_smem);
    asm volatile("cp.async.cg.shared.global [%0],[%1],16;"::"r"(d),"l"(src):"memory");
}

// ---------------- fused embedding gather + bf16 split (layer-1 A) ----------
// writes g_EMB (fp32, for GCN) and g_A3 rows (hi|hi|lo, K=256)
__global__ void k_embsplit(const int* __restrict__ seq, const float* __restrict__ tab){
    int m = blockIdx.x; int s = m>>6, b = m&63;
    long tok = seq[b*512+s];
    int t = threadIdx.x;                       // 64 threads, 4 floats each
    float4 v = ((const float4*)(tab + tok*256))[t];
    ((float4*)(g_EMB + (long)m*256))[t] = v;
    __nv_bfloat16 h0=__float2bfloat16(v.x), h1=__float2bfloat16(v.y);
    __nv_bfloat16 h2=__float2bfloat16(v.z), h3=__float2bfloat16(v.w);
    __nv_bfloat16 l0=__float2bfloat16(v.x-__bfloat162float(h0));
    __nv_bfloat16 l1=__float2bfloat16(v.y-__bfloat162float(h1));
    __nv_bfloat16 l2=__float2bfloat16(v.z-__bfloat162float(h2));
    __nv_bfloat16 l3=__float2bfloat16(v.w-__bfloat162float(h3));
    ushort4 hh = make_ushort4(__bfloat16_as_ushort(h0),__bfloat16_as_ushort(h1),
                              __bfloat16_as_ushort(h2),__bfloat16_as_ushort(h3));
    ushort4 ll = make_ushort4(__bfloat16_as_ushort(l0),__bfloat16_as_ushort(l1),
                              __bfloat16_as_ushort(l2),__bfloat16_as_ushort(l3));
    unsigned short* yp = (unsigned short*)(g_A3 + (long)m*768 + t*4);
    *(ushort4*)yp = hh;
    *(ushort4*)(yp + 256) = hh;
    *(ushort4*)(yp + 512) = ll;
}

__global__ void k_rst(){ g_barG[threadIdx.x] = 0u; }

// ---------------- bf16 split conversions ----------------
__global__ void k_splitA(const float* __restrict__ X, __nv_bfloat16* __restrict__ Y, int K){
    long idx = (long)blockIdx.x*256 + threadIdx.x;
    int kq = K>>2;
    long m = idx/kq; int k4 = (int)(idx - m*kq)*4;
    float4 v = *(const float4*)(X + m*K + k4);
    __nv_bfloat16 h0=__float2bfloat16(v.x), h1=__float2bfloat16(v.y);
    __nv_bfloat16 h2=__float2bfloat16(v.z), h3=__float2bfloat16(v.w);
    __nv_bfloat16 l0=__float2bfloat16(v.x-__bfloat162float(h0));
    __nv_bfloat16 l1=__float2bfloat16(v.y-__bfloat162float(h1));
    __nv_bfloat16 l2=__float2bfloat16(v.z-__bfloat162float(h2));
    __nv_bfloat16 l3=__float2bfloat16(v.w-__bfloat162float(h3));
    ushort4 hh = make_ushort4(__bfloat16_as_ushort(h0),__bfloat16_as_ushort(h1),
                              __bfloat16_as_ushort(h2),__bfloat16_as_ushort(h3));
    ushort4 ll = make_ushort4(__bfloat16_as_ushort(l0),__bfloat16_as_ushort(l1),
                              __bfloat16_as_ushort(l2),__bfloat16_as_ushort(l3));
    unsigned short* yp = (unsigned short*)(Y + m*3L*K + k4);
    *(ushort4*)yp = hh;
    *(ushort4*)(yp + K) = hh;
    *(ushort4*)(yp + 2*K) = ll;
}
// weights: Y[n][0:K]=hi, [K:2K]=lo, [2K:3K]=hi ; block 0 also resets barriers
__global__ void k_splitW(const float* __restrict__ X, __nv_bfloat16* __restrict__ Y, int K){
    if(blockIdx.x==0){
        g_barG[threadIdx.x] = 0u;
        g_barG[256+threadIdx.x] = 0u;
    }
    long idx = (long)blockIdx.x*256 + threadIdx.x;
    int kq = K>>2;
    long m = idx/kq; int k4 = (int)(idx - m*kq)*4;
    float4 v = *(const float4*)(X + m*K + k4);
    __nv_bfloat16 h0=__float2bfloat16(v.x), h1=__float2bfloat16(v.y);
    __nv_bfloat16 h2=__float2bfloat16(v.z), h3=__float2bfloat16(v.w);
    __nv_bfloat16 l0=__float2bfloat16(v.x-__bfloat162float(h0));
    __nv_bfloat16 l1=__float2bfloat16(v.y-__bfloat162float(h1));
    __nv_bfloat16 l2=__float2bfloat16(v.z-__bfloat162float(h2));
    __nv_bfloat16 l3=__float2bfloat16(v.w-__bfloat162float(h3));
    ushort4 hh = make_ushort4(__bfloat16_as_ushort(h0),__bfloat16_as_ushort(h1),
                              __bfloat16_as_ushort(h2),__bfloat16_as_ushort(h3));
    ushort4 ll = make_ushort4(__bfloat16_as_ushort(l0),__bfloat16_as_ushort(l1),
                              __bfloat16_as_ushort(l2),__bfloat16_as_ushort(l3));
    unsigned short* yp = (unsigned short*)(Y + m*3L*K + k4);
    *(ushort4*)yp = hh;
    *(ushort4*)(yp + K) = ll;
    *(ushort4*)(yp + 2*K) = hh;
}

// ---------------- tensor-core GEMM (unchanged) ----------------
#define SPAD 72
__global__ void __launch_bounds__(256,2) k_mma(const __nv_bfloat16* __restrict__ A,
        const __nv_bfloat16* __restrict__ W, const float* __restrict__ bias,
        float* __restrict__ C, int Ks, int N){
    __shared__ __align__(16) __nv_bfloat16 As[128*SPAD];
    __shared__ __align__(16) __nv_bfloat16 Bs[128*SPAD];
    int tid = threadIdx.x;
    int m0 = blockIdx.y*128, n0 = blockIdx.x*128;
    int warp = tid>>5, lane = tid&31;
    int wm = (warp>>1)*32, wn = (warp&1)*64;
    int gid = lane>>2, tig = lane&3;
    float acc[2][8][4];
#pragma unroll
    for(int i=0;i<2;i++)
#pragma unroll
        for(int j=0;j<8;j++){ acc[i][j][0]=0.f; acc[i][j][1]=0.f; acc[i][j][2]=0.f; acc[i][j][3]=0.f; }
    for(int kt=0; kt<Ks; kt+=64){
#pragma unroll
        for(int i=0;i<4;i++){
            int idx = i*256 + tid;
            int r = idx>>3, c = (idx&7)*8;
            *(float4*)&As[r*SPAD + c] = *(const float4*)(A + (long)(m0+r)*Ks + kt + c);
            *(float4*)&Bs[r*SPAD + c] = *(const float4*)(W + (long)(n0+r)*Ks + kt + c);
        }
        __syncthreads();
#pragma unroll
        for(int kk=0;kk<4;kk++){
            unsigned a[2][4];
#pragma unroll
            for(int mt=0;mt<2;mt++){
                const __nv_bfloat16* ab = &As[(wm+mt*16+gid)*SPAD + kk*16 + tig*2];
                a[mt][0] = *(const unsigned*)ab;
                a[mt][1] = *(const unsigned*)(ab + 8*SPAD);
                a[mt][2] = *(const unsigned*)(ab + 8);
                a[mt][3] = *(const unsigned*)(ab + 8*SPAD + 8);
            }
#pragma unroll
            for(int nt=0;nt<8;nt++){
                const __nv_bfloat16* bb = &Bs[(wn+nt*8+gid)*SPAD + kk*16 + tig*2];
                unsigned b0 = *(const unsigned*)bb;
                unsigned b1 = *(const unsigned*)(bb + 8);
#pragma unroll
                for(int mt=0;mt<2;mt++){
                    asm volatile(
                        "mma.sync.aligned.m16n8k16.row.col.f32.bf16.bf16.f32 "
                        "{%0,%1,%2,%3},{%4,%5,%6,%7},{%8,%9},{%0,%1,%2,%3};\n"
                        : "+f"(acc[mt][nt][0]), "+f"(acc[mt][nt][1]),
                          "+f"(acc[mt][nt][2]), "+f"(acc[mt][nt][3])
                        : "r"(a[mt][0]), "r"(a[mt][1]), "r"(a[mt][2]), "r"(a[mt][3]),
                          "r"(b0), "r"(b1));
                }
            }
        }
        __syncthreads();
    }
#pragma unroll
    for(int mt=0;mt<2;mt++){
#pragma unroll
        for(int nt=0;nt<8;nt++){
            int row = m0 + wm + mt*16 + gid;
            int col = n0 + wn + nt*8 + tig*2;
            float b0v = bias[col], b1v = bias[col+1];
            *(float2*)&C[(long)row*N + col] =
                make_float2(acc[mt][nt][0]+b0v, acc[mt][nt][1]+b1v);
            *(float2*)&C[(long)(row+8)*N + col] =
                make_float2(acc[mt][nt][2]+b0v, acc[mt][nt][3]+b1v);
        }
    }
}

// ---------------- persistent bidirectional LSTM (R13 best + all-thread poll)
#define PSP 18
#define LSM ((4096 + 4*64*PSP)*4)

__global__ void __launch_bounds__(256) k_lstm(const float* __restrict__ gates,
        const float* __restrict__ WhhA, const float* __restrict__ WhhB,
        float* __restrict__ out){
    extern __shared__ float sm[];
    float* hshF = sm;            // [256k][8b]
    float* hshB = sm + 2048;
    float* ps   = sm + 4096;     // [4q][64r][PSP]
    int tid = threadIdx.x, bid = blockIdx.x;
    int hb = bid&15, bg = bid>>4;
    int hu0 = hb*16, b0 = bg*8;
    int r = tid&63, q = tid>>6;
    int gate = r>>4, ru = r&15;
    float4 wf[16], wb[16];
    {
        const float* wsf = WhhA + (long)(gate*256+hu0+ru)*256 + q*64;
        const float* wsb = WhhB + (long)(gate*256+hu0+ru)*256 + q*64;
#pragma unroll
        for(int j=0;j<16;j++){ wf[j] = *(const float4*)(wsf+j*4);
                               wb[j] = *(const float4*)(wsb+j*4); }
    }
    unsigned* ctrF = &g_barG[(0*8+bg)*32];
    unsigned* ctrB = &g_barG[(1*8+bg)*32];
    int cu = tid>>3, cb = tid&7;         // combine mapping, tid<128
    float cf = 0.f, cbk = 0.f;
    if(tid<128){
        g_H[(((long)0*2+0)*8+bg)*2048 + (hu0+cu)*8+cb] = 0.f;
        g_H[(((long)0*2+1)*8+bg)*2048 + (hu0+cu)*8+cb] = 0.f;
    }
    __syncthreads();
    if(tid==0){ bar_arrive(ctrF); bar_arrive(ctrB); }
    unsigned tgt = 16;
    const float* hqF = hshF + q*512;
    const float* hqB = hshB + q*512;
    for(int si=0; si<512; si++){
        int sF = si, sB = 511-si;
        int pp = si&1;
        // gate prefetch (registers; overlaps polls)
        float xiF,xfF,xgF,xoF, xiB,xfB,xgB,xoB;
        if(tid<128){
            long gbF = ((long)sF*64 + b0+cb)*2048 + hu0+cu;
            long gbB = ((long)sB*64 + b0+cb)*2048 + 1024 + hu0+cu;
            xiF=__ldg(gates+gbF); xfF=__ldg(gates+gbF+256);
            xgF=__ldg(gates+gbF+512); xoF=__ldg(gates+gbF+768);
            xiB=__ldg(gates+gbB); xfB=__ldg(gates+gbB+256);
            xgB=__ldg(gates+gbB+512); xoB=__ldg(gates+gbB+768);
        }
        bar_poll(ctrF, tgt);                 // all threads
        // stage F (direct ldcg, own slots)
        {
            const float* srcF = g_H + (((long)pp*2+0)*8+bg)*2048;
            float4 f0 = __ldcg((const float4*)(srcF + tid*4));
            float4 f1 = __ldcg((const float4*)(srcF + 1024 + tid*4));
            *(float4*)&hshF[tid*4] = f0; *(float4*)&hshF[1024+tid*4] = f1;
        }
        bar_poll(ctrB, tgt);                 // all threads
        __syncthreads();
        // stage B via cp.async (hidden under fwd dot)
        {
            const float* srcB = g_H + (((long)pp*2+1)*8+bg)*2048;
            cpasync16(&hshB[tid*4], srcB + tid*4);
            cpasync16(&hshB[1024+tid*4], srcB + 1024 + tid*4);
            asm volatile("cp.async.commit_group;":::"memory");
        }
        // ---- fwd dot ----
        {
            unsigned long long a0=0,a1=0,a2=0,a3=0;
#pragma unroll
            for(int j4=0;j4<16;j4++){
                float4 w4 = wf[j4];
                const ulonglong2* hp = (const ulonglong2*)(hqF + j4*32);
                ulonglong2 p0=hp[0],p1=hp[1],p2=hp[2],p3=hp[3];
                ulonglong2 p4=hp[4],p5=hp[5],p6=hp[6],p7=hp[7];
                unsigned long long w;
                w=pk2f(w4.x,w4.x); fma2(a0,w,p0.x);fma2(a1,w,p0.y);fma2(a2,w,p1.x);fma2(a3,w,p1.y);
                w=pk2f(w4.y,w4.y); fma2(a0,w,p2.x);fma2(a1,w,p2.y);fma2(a2,w,p3.x);fma2(a3,w,p3.y);
                w=pk2f(w4.z,w4.z); fma2(a0,w,p4.x);fma2(a1,w,p4.y);fma2(a2,w,p5.x);fma2(a3,w,p5.y);
                w=pk2f(w4.w,w4.w); fma2(a0,w,p6.x);fma2(a1,w,p6.y);fma2(a2,w,p7.x);fma2(a3,w,p7.y);
            }
            unsigned long long* pr = (unsigned long long*)&ps[(q*64+r)*PSP];
            pr[0]=a0; pr[1]=a1; pr[2]=a2; pr[3]=a3;
        }
        asm volatile("cp.async.wait_group 0;":::"memory");
        __syncthreads();
        if(tid<128){
            #define RDQ(g) (ps[((g)*16+cu)*PSP+cb]+ps[(64+(g)*16+cu)*PSP+cb]+ \
                            ps[(128+(g)*16+cu)*PSP+cb]+ps[(192+(g)*16+cu)*PSP+cb])
            float gi = RDQ(0)+xiF, gf = RDQ(1)+xfF, gg = RDQ(2)+xgF, go = RDQ(3)+xoF;
            cf = sigm(gf)*cf + sigm(gi)*tanhf(gg);
            float h = sigm(go)*tanhf(cf);
            __stcg(&g_H[(((long)(1-pp)*2+0)*8+bg)*2048 + (hu0+cu)*8+cb], h);
            out[((long)sF*64 + b0+cb)*512 + hu0+cu] = h;
        }
        __syncthreads();
        if(tid==0) bar_arrive(ctrF);
        // ---- bwd dot ----
        {
            unsigned long long a0=0,a1=0,a2=0,a3=0;
#pragma unroll
            for(int j4=0;j4<16;j4++){
                float4 w4 = wb[j4];
                const ulonglong2* hp = (const ulonglong2*)(hqB + j4*32);
                ulonglong2 p0=hp[0],p1=hp[1],p2=hp[2],p3=hp[3];
                ulonglong2 p4=hp[4],p5=hp[5],p6=hp[6],p7=hp[7];
                unsigned long long w;
                w=pk2f(w4.x,w4.x); fma2(a0,w,p0.x);fma2(a1,w,p0.y);fma2(a2,w,p1.x);fma2(a3,w,p1.y);
                w=pk2f(w4.y,w4.y); fma2(a0,w,p2.x);fma2(a1,w,p2.y);fma2(a2,w,p3.x);fma2(a3,w,p3.y);
                w=pk2f(w4.z,w4.z); fma2(a0,w,p4.x);fma2(a1,w,p4.y);fma2(a2,w,p5.x);fma2(a3,w,p5.y);
                w=pk2f(w4.w,w4.w); fma2(a0,w,p6.x);fma2(a1,w,p6.y);fma2(a2,w,p7.x);fma2(a3,w,p7.y);
            }
            unsigned long long* pr = (unsigned long long*)&ps[(q*64+r)*PSP];
            pr[0]=a0; pr[1]=a1; pr[2]=a2; pr[3]=a3;
        }
        __syncthreads();
        if(tid<128){
            float gi = RDQ(0)+xiB, gf = RDQ(1)+xfB, gg = RDQ(2)+xgB, go = RDQ(3)+xoB;
            cbk = sigm(gf)*cbk + sigm(gi)*tanhf(gg);
            float h = sigm(go)*tanhf(cbk);
            __stcg(&g_H[(((long)(1-pp)*2+1)*8+bg)*2048 + (hu0+cu)*8+cb], h);
            out[((long)sB*64 + b0+cb)*512 + 256 + hu0+cu] = h;
        }
        __syncthreads();
        if(tid==0) bar_arrive(ctrB);
        tgt += 16;
    }
}

// ---------------- GCN banded adjacency ----------------
__global__ void k_band(const float* __restrict__ x, const float* __restrict__ mask,
                       float* __restrict__ o){
    int m = blockIdx.x; int s=m>>6, b=m&63;
    float mm = mask[b*512+s];
    float mn = (s<511)? mask[b*512+s+1] : 0.f;
    float mp = (s>0)?   mask[b*512+s-1] : 0.f;
    float rs = mm*(mp+mn)+1e-8f;
    float cn = mm*mn/rs, cp = mm*mp/rs;
    int t = threadIdx.x;
    float4 vn = (s<511)? ((const float4*)(x+((long)m+64)*256))[t] : make_float4(0,0,0,0);
    float4 vp = (s>0)?   ((const float4*)(x+((long)m-64)*256))[t] : make_float4(0,0,0,0);
    float4 r; r.x=cn*vn.x+cp*vp.x; r.y=cn*vn.y+cp*vp.y;
    r.z=cn*vn.z+cp*vp.z; r.w=cn*vn.w+cp*vp.w;
    ((float4*)(o+(long)m*256))[t]=r;
}

// ---------------- residual + LayerNorm + ReLU ----------------
__global__ void k_ln(const float* __restrict__ go, const float* __restrict__ xin,
                     const float* __restrict__ gamma, const float* __restrict__ beta,
                     float* __restrict__ o){
    __shared__ float rs1[8], rs2[8];
    long m = blockIdx.x; int t = threadIdx.x;
    float v = go[m*256+t] + xin[m*256+t];
    float s1=v, s2=v*v;
#pragma unroll
    for(int w=16;w;w>>=1){ s1+=__shfl_xor_sync(~0u,s1,w); s2+=__shfl_xor_sync(~0u,s2,w); }
    if((t&31)==0){ rs1[t>>5]=s1; rs2[t>>5]=s2; }
    __syncthreads();
    float S1=0,S2=0;
#pragma unroll
    for(int i=0;i<8;i++){ S1+=rs1[i]; S2+=rs2[i]; }
    float mu=S1*(1.f/256.f), var=S2*(1.f/256.f)-mu*mu;
    float inv=rsqrtf(var+1e-5f);
    float y=(v-mu)*inv*gamma[t]+beta[t];
    o[m*256+t]=fmaxf(y,0.f);
}

// ---------------- masked mean pooling + fuse ----------------
__global__ void k_pool(const float* __restrict__ lstm, const float* __restrict__ gcn,
                       const float* __restrict__ mask, const float* __restrict__ aux){
    int b = blockIdx.x, t = threadIdx.x;
    float dn=0.f;
    for(int s=0;s<512;s++) dn += mask[b*512+s];
    dn = fmaxf(dn,1e-8f);
    float acc=0.f;
    for(int s=0;s<512;s++) acc += lstm[((long)s*64+b)*512+t]*mask[b*512+s];
    g_FU[b*774+t]=acc/dn;
    if(t<256){
        float a2=0.f;
        for(int s=0;s<512;s++) a2 += gcn[((long)s*64+b)*256+t]*mask[b*512+s];
        g_FU[b*774+512+t]=a2/dn;
    }
    if(t<6) g_FU[b*774+768+t]=aux[b*6+t];
}

// ---------------- small FC ----------------
__global__ void k_fc(const float* __restrict__ in, const float* __restrict__ W,
                     const float* __restrict__ bias, float* __restrict__ o,
                     int K, int N, int relu){
    int idx = blockIdx.x*blockDim.x + threadIdx.x;
    if(idx >= 64*N) return;
    int b = idx/N, n = idx%N;
    const float* ip = in + (long)b*K;
    const float* wp = W + (long)n*K;
    float a=0.f;
    for(int k=0;k<K;k++) a += ip[k]*wp[k];
    a += bias[n];
    o[idx] = relu ? fmaxf(a,0.f) : a;
}

// ---------------- launch ----------------
extern "C" void kernel_launch(void* const* d_in, const int* in_sizes, int n_in,
                              void* d_out, int out_size){
    const int*   seq  = (const int*)  d_in[0];
    const float* mask = (const float*)d_in[1];
    const float* aux  = (const float*)d_in[2];
    const float* emb  = (const float*)d_in[3];
    const float* Wih0 = (const float*)d_in[4];
    const float* Whh0 = (const float*)d_in[5];
    const float* b0   = (const float*)d_in[6];
    const float* WihL = (const float*)d_in[7];
    const float* WhhL = (const float*)d_in[8];
    const float* bLp  = (const float*)d_in[9];
    const float* gW   = (const float*)d_in[10];
    const float* gb   = (const float*)d_in[11];
    const float* gga  = (const float*)d_in[12];
    const float* gbe  = (const float*)d_in[13];
    const float* f1W  = (const float*)d_in[14];
    const float* f1b  = (const float*)d_in[15];
    const float* f2W  = (const float*)d_in[16];
    const float* f2b  = (const float*)d_in[17];
    const float* h0W  = (const float*)d_in[18];
    const float* h0b  = (const float*)d_in[19];
    const float* h1W  = (const float*)d_in[20];
    const float* h1b  = (const float*)d_in[21];
    float* out = (float*)d_out;

    float *pEMB,*pXA,*pXB,*pGT,*pT0,*pT1,*pP0,*pP1,*pFU,*pS1,*pS2;
    __nv_bfloat16 *pA3,*pW3,*pW3G;
    cudaGetSymbolAddress((void**)&pEMB,g_EMB);
    cudaGetSymbolAddress((void**)&pXA, g_XA);
    cudaGetSymbolAddress((void**)&pXB, g_XB);
    cudaGetSymbolAddress((void**)&pGT, g_GT);
    cudaGetSymbolAddress((void**)&pT0, g_T0);
    cudaGetSymbolAddress((void**)&pT1, g_T1);
    cudaGetSymbolAddress((void**)&pP0, g_P0);
    cudaGetSymbolAddress((void**)&pP1, g_P1);
    cudaGetSymbolAddress((void**)&pFU, g_FU);
    cudaGetSymbolAddress((void**)&pS1, g_S1);
    cudaGetSymbolAddress((void**)&pS2, g_S2);
    cudaGetSymbolAddress((void**)&pA3, g_A3);
    cudaGetSymbolAddress((void**)&pW3, g_W3);
    cudaGetSymbolAddress((void**)&pW3G,g_W3G);
    cudaFuncSetAttribute(k_lstm, cudaFuncAttributeMaxDynamicSharedMemorySize, LSM);

    // launch order: k_lstm at index 3 (the slot ncu -s 5 -c 1 actually captures)
    k_embsplit<<<32768,64>>>(seq, emb);                    // 0: emb + layer-1 splitA
    k_splitW<<<512,256>>>(Wih0, pW3, 256);                 // 1: + barrier reset
    {   dim3 gg(2048/128, 32768/128);
        k_mma<<<gg,256>>>(pA3, pW3, b0, pGT, 768, 2048);   // 2
    }
    float* lo = pXA;
    k_lstm<<<128,256,LSM>>>(pGT, Whh0, Whh0 + 1024*256, lo);   // 3 <- ncu
    const float* inp = lo;
    for(int l=1;l<5;l++){
        const float* wih = WihL + (long)(l-1)*2*1024*512;
        const float* whh = WhhL + (long)(l-1)*2*1024*256;
        const float* bb  = bLp  + (long)(l-1)*2*1024;
        k_splitA<<<16384,256>>>(inp, pA3, 512);
        k_splitW<<<1024,256>>>(wih, pW3, 512);
        dim3 gg(2048/128, 32768/128);
        k_mma<<<gg,256>>>(pA3, pW3, bb, pGT, 1536, 2048);
        k_rst<<<1,512>>>();
        lo = (l&1) ? pXB : pXA;
        k_lstm<<<128,256,LSM>>>(pGT, whh, whh + 1024*256, lo);
        inp = lo;
    }
    const float* lstmOut = lo;

    k_splitW<<<64,256>>>(gW,             pW3G,            256);
    k_splitW<<<64,256>>>(gW + 256*256,   pW3G + 196608,   256);
    k_splitW<<<64,256>>>(gW + 2*256*256, pW3G + 2*196608, 256);

    const float* gin = pEMB;
    float* gout = pP0;
    for(int i=0;i<3;i++){
        k_band<<<32768,64>>>(gin, mask, pT0);
        k_splitA<<<8192,256>>>(pT0, pA3, 256);
        dim3 gg(256/128, 32768/128);
        k_mma<<<gg,256>>>(pA3, pW3G + (long)i*196608, gb + i*256, pT1, 768, 256);
        gout = (i&1) ? pP1 : pP0;
        k_ln<<<32768,256>>>(pT1, gin, gga + i*256, gbe + i*256, gout);
        gin = gout;
    }

    k_pool<<<64,512>>>(lstmOut, gout, mask, aux);
    k_fc<<<(64*512+255)/256,256>>>(pFU, f1W, f1b, pS1, 774, 512, 1);
    k_fc<<<(64*256+255)/256,256>>>(pS1, f2W, f2b, pS2, 512, 256, 1);
    k_fc<<<(64*10+255)/256,256>>>(pS2, h0W, h0b, out,      256, 10, 0);
    k_fc<<<(64*5 +255)/256,256>>>(pS2, h1W, h1b, out+640, 256,  5, 0);
}

// round 16
// speedup vs baseline: 1.4144x; 1.1219x over previous
#include <cuda_runtime.h>
#include <cuda_bf16.h>
#include <math.h>

// ---------------- static scratch ----------------
__device__ __align__(256) float g_EMB[512*64*256];
__device__ __align__(256) float g_XA [512*64*512];
__device__ __align__(256) float g_XB [512*64*512];
__device__ __align__(256) float g_GT [512*64*2048];
__device__ __align__(256) float g_T0 [512*64*256];
__device__ __align__(256) float g_T1 [512*64*256];
__device__ __align__(256) float g_P0 [512*64*256];
__device__ __align__(256) float g_P1 [512*64*256];
__device__ __align__(256) float g_H  [2*2*8*256*8];  // [pp][dir][bg][k][8b]
__device__ __align__(256) float g_FU [64*774];
__device__ __align__(256) float g_S1 [64*512];
__device__ __align__(256) float g_S2 [64*256];
__device__ __align__(256) __nv_bfloat16 g_A3 [32768L*1536];
__device__ __align__(256) __nv_bfloat16 g_W3 [2048L*1536];
__device__ __align__(256) __nv_bfloat16 g_W3G[3L*256*768];
__device__ unsigned g_barG[512];                     // 16 counters, 128B apart

// ---------------- helpers ----------------
__device__ __forceinline__ float sigm(float x){ return 1.f/(1.f+__expf(-x)); }
__device__ __forceinline__ unsigned long long pk2f(float lo, float hi){
    unsigned long long u; asm("mov.b64 %0,{%1,%2};":"=l"(u):"f"(lo),"f"(hi)); return u;
}
__device__ __forceinline__ void fma2(unsigned long long&d,unsigned long long a,unsigned long long b){
    asm("fma.rn.f32x2 %0,%1,%2,%0;":"+l"(d):"l"(a),"l"(b));
}
__device__ __forceinline__ void bar_arrive(unsigned* c){
    asm volatile("red.release.gpu.global.add.u32 [%0],1;"::"l"(c):"memory");
}
__device__ __forceinline__ void bar_poll(unsigned* c, unsigned tgt){
    unsigned v;
    while(1){
        asm volatile("ld.acquire.gpu.global.u32 %0,[%1];":"=r"(v):"l"(c):"memory");
        if(v>=tgt) break;
        __nanosleep(20);
    }
}
__device__ __forceinline__ void nbar(int id){
    asm volatile("bar.sync %0,128;"::"r"(id):"memory");
}

// ---------------- fused embedding gather + bf16 split (layer-1 A) ----------
__global__ void k_embsplit(const int* __restrict__ seq, const float* __restrict__ tab){
    int m = blockIdx.x; int s = m>>6, b = m&63;
    long tok = seq[b*512+s];
    int t = threadIdx.x;
    float4 v = ((const float4*)(tab + tok*256))[t];
    ((float4*)(g_EMB + (long)m*256))[t] = v;
    __nv_bfloat16 h0=__float2bfloat16(v.x), h1=__float2bfloat16(v.y);
    __nv_bfloat16 h2=__float2bfloat16(v.z), h3=__float2bfloat16(v.w);
    __nv_bfloat16 l0=__float2bfloat16(v.x-__bfloat162float(h0));
    __nv_bfloat16 l1=__float2bfloat16(v.y-__bfloat162float(h1));
    __nv_bfloat16 l2=__float2bfloat16(v.z-__bfloat162float(h2));
    __nv_bfloat16 l3=__float2bfloat16(v.w-__bfloat162float(h3));
    ushort4 hh = make_ushort4(__bfloat16_as_ushort(h0),__bfloat16_as_ushort(h1),
                              __bfloat16_as_ushort(h2),__bfloat16_as_ushort(h3));
    ushort4 ll = make_ushort4(__bfloat16_as_ushort(l0),__bfloat16_as_ushort(l1),
                              __bfloat16_as_ushort(l2),__bfloat16_as_ushort(l3));
    unsigned short* yp = (unsigned short*)(g_A3 + (long)m*768 + t*4);
    *(ushort4*)yp = hh;
    *(ushort4*)(yp + 256) = hh;
    *(ushort4*)(yp + 512) = ll;
}

__global__ void k_rst(){ g_barG[threadIdx.x] = 0u; }

// ---------------- bf16 split conversions ----------------
__global__ void k_splitA(const float* __restrict__ X, __nv_bfloat16* __restrict__ Y, int K){
    long idx = (long)blockIdx.x*256 + threadIdx.x;
    int kq = K>>2;
    long m = idx/kq; int k4 = (int)(idx - m*kq)*4;
    float4 v = *(const float4*)(X + m*K + k4);
    __nv_bfloat16 h0=__float2bfloat16(v.x), h1=__float2bfloat16(v.y);
    __nv_bfloat16 h2=__float2bfloat16(v.z), h3=__float2bfloat16(v.w);
    __nv_bfloat16 l0=__float2bfloat16(v.x-__bfloat162float(h0));
    __nv_bfloat16 l1=__float2bfloat16(v.y-__bfloat162float(h1));
    __nv_bfloat16 l2=__float2bfloat16(v.z-__bfloat162float(h2));
    __nv_bfloat16 l3=__float2bfloat16(v.w-__bfloat162float(h3));
    ushort4 hh = make_ushort4(__bfloat16_as_ushort(h0),__bfloat16_as_ushort(h1),
                              __bfloat16_as_ushort(h2),__bfloat16_as_ushort(h3));
    ushort4 ll = make_ushort4(__bfloat16_as_ushort(l0),__bfloat16_as_ushort(l1),
                              __bfloat16_as_ushort(l2),__bfloat16_as_ushort(l3));
    unsigned short* yp = (unsigned short*)(Y + m*3L*K + k4);
    *(ushort4*)yp = hh;
    *(ushort4*)(yp + K) = hh;
    *(ushort4*)(yp + 2*K) = ll;
}
__global__ void k_splitW(const float* __restrict__ X, __nv_bfloat16* __restrict__ Y, int K){
    if(blockIdx.x==0){
        g_barG[threadIdx.x] = 0u;
        g_barG[256+threadIdx.x] = 0u;
    }
    long idx = (long)blockIdx.x*256 + threadIdx.x;
    int kq = K>>2;
    long m = idx/kq; int k4 = (int)(idx - m*kq)*4;
    float4 v = *(const float4*)(X + m*K + k4);
    __nv_bfloat16 h0=__float2bfloat16(v.x), h1=__float2bfloat16(v.y);
    __nv_bfloat16 h2=__float2bfloat16(v.z), h3=__float2bfloat16(v.w);
    __nv_bfloat16 l0=__float2bfloat16(v.x-__bfloat162float(h0));
    __nv_bfloat16 l1=__float2bfloat16(v.y-__bfloat162float(h1));
    __nv_bfloat16 l2=__float2bfloat16(v.z-__bfloat162float(h2));
    __nv_bfloat16 l3=__float2bfloat16(v.w-__bfloat162float(h3));
    ushort4 hh = make_ushort4(__bfloat16_as_ushort(h0),__bfloat16_as_ushort(h1),
                              __bfloat16_as_ushort(h2),__bfloat16_as_ushort(h3));
    ushort4 ll = make_ushort4(__bfloat16_as_ushort(l0),__bfloat16_as_ushort(l1),
                              __bfloat16_as_ushort(l2),__bfloat16_as_ushort(l3));
    unsigned short* yp = (unsigned short*)(Y + m*3L*K + k4);
    *(ushort4*)yp = hh;
    *(ushort4*)(yp + K) = ll;
    *(ushort4*)(yp + 2*K) = hh;
}

// ---------------- tensor-core GEMM (unchanged) ----------------
#define SPAD 72
__global__ void __launch_bounds__(256,2) k_mma(const __nv_bfloat16* __restrict__ A,
        const __nv_bfloat16* __restrict__ W, const float* __restrict__ bias,
        float* __restrict__ C, int Ks, int N){
    __shared__ __align__(16) __nv_bfloat16 As[128*SPAD];
    __shared__ __align__(16) __nv_bfloat16 Bs[128*SPAD];
    int tid = threadIdx.x;
    int m0 = blockIdx.y*128, n0 = blockIdx.x*128;
    int warp = tid>>5, lane = tid&31;
    int wm = (warp>>1)*32, wn = (warp&1)*64;
    int gid = lane>>2, tig = lane&3;
    float acc[2][8][4];
#pragma unroll
    for(int i=0;i<2;i++)
#pragma unroll
        for(int j=0;j<8;j++){ acc[i][j][0]=0.f; acc[i][j][1]=0.f; acc[i][j][2]=0.f; acc[i][j][3]=0.f; }
    for(int kt=0; kt<Ks; kt+=64){
#pragma unroll
        for(int i=0;i<4;i++){
            int idx = i*256 + tid;
            int r = idx>>3, c = (idx&7)*8;
            *(float4*)&As[r*SPAD + c] = *(const float4*)(A + (long)(m0+r)*Ks + kt + c);
            *(float4*)&Bs[r*SPAD + c] = *(const float4*)(W + (long)(n0+r)*Ks + kt + c);
        }
        __syncthreads();
#pragma unroll
        for(int kk=0;kk<4;kk++){
            unsigned a[2][4];
#pragma unroll
            for(int mt=0;mt<2;mt++){
                const __nv_bfloat16* ab = &As[(wm+mt*16+gid)*SPAD + kk*16 + tig*2];
                a[mt][0] = *(const unsigned*)ab;
                a[mt][1] = *(const unsigned*)(ab + 8*SPAD);
                a[mt][2] = *(const unsigned*)(ab + 8);
                a[mt][3] = *(const unsigned*)(ab + 8*SPAD + 8);
            }
#pragma unroll
            for(int nt=0;nt<8;nt++){
                const __nv_bfloat16* bb = &Bs[(wn+nt*8+gid)*SPAD + kk*16 + tig*2];
                unsigned b0 = *(const unsigned*)bb;
                unsigned b1 = *(const unsigned*)(bb + 8);
#pragma unroll
                for(int mt=0;mt<2;mt++){
                    asm volatile(
                        "mma.sync.aligned.m16n8k16.row.col.f32.bf16.bf16.f32 "
                        "{%0,%1,%2,%3},{%4,%5,%6,%7},{%8,%9},{%0,%1,%2,%3};\n"
                        : "+f"(acc[mt][nt][0]), "+f"(acc[mt][nt][1]),
                          "+f"(acc[mt][nt][2]), "+f"(acc[mt][nt][3])
                        : "r"(a[mt][0]), "r"(a[mt][1]), "r"(a[mt][2]), "r"(a[mt][3]),
                          "r"(b0), "r"(b1));
                }
            }
        }
        __syncthreads();
    }
#pragma unroll
    for(int mt=0;mt<2;mt++){
#pragma unroll
        for(int nt=0;nt<8;nt++){
            int row = m0 + wm + mt*16 + gid;
            int col = n0 + wn + nt*8 + tig*2;
            float b0v = bias[col], b1v = bias[col+1];
            *(float2*)&C[(long)row*N + col] =
                make_float2(acc[mt][nt][0]+b0v, acc[mt][nt][1]+b1v);
            *(float2*)&C[(long)(row+8)*N + col] =
                make_float2(acc[mt][nt][2]+b0v, acc[mt][nt][3]+b1v);
        }
    }
}

// ---------------- persistent LSTM: warp-specialized fwd/bwd ----------------
// 128 CTAs = bg(8 of 8 batch) x hb(16 of 16 units). Warps 0-3 run fwd,
// warps 4-7 run bwd, fully independent chains (own weights, smem, counter,
// named barrier). Exchange latencies of the two dirs overlap on the SM.
#define PSP 10
#define LSM ((4096 + 2*2*64*PSP)*4)

__global__ void __launch_bounds__(256) k_lstm(const float* __restrict__ gates,
        const float* __restrict__ WhhA, const float* __restrict__ WhhB,
        float* __restrict__ out){
    extern __shared__ float sm[];
    // [half]: hsh 2048, ps 2*64*PSP
    int tid = threadIdx.x, bid = blockIdx.x;
    int hb = bid&15, bg = bid>>4;
    int hu0 = hb*16, b0 = bg*8;
    int half = tid>>7;               // 0 = fwd, 1 = bwd
    int ht = tid&127;
    float* hsh = sm + half*2048;
    float* ps  = sm + 4096 + half*(2*64*PSP);
    int r = ht&63, q = ht>>6;        // row (4 gates x 16 units), k-half
    int gate = r>>4, ru = r&15;
    const float* Whh = half ? WhhB : WhhA;
    float4 wreg[32];                 // 128 k-floats of own row
    {
        const float* wsrc = Whh + (long)(gate*256+hu0+ru)*256 + q*128;
#pragma unroll
        for(int j=0;j<32;j++) wreg[j] = *(const float4*)(wsrc + j*4);
    }
    unsigned* ctr = &g_barG[(half*8+bg)*32];
    int cu = ht>>3, cb = ht&7;       // combine: 16 units x 8 batch
    float c = 0.f;
    int nb = 1 + half;
    g_H[(((long)0*2+half)*8+bg)*2048 + (hu0+cu)*8+cb] = 0.f;   // pp=0 own dir
    nbar(nb);
    if(ht==0) bar_arrive(ctr);
    unsigned tgt = 16;
    const float* hq = hsh + q*1024;
    for(int si=0; si<512; si++){
        int s = half ? 511-si : si;
        int pp = si&1;
        // gate prefetch (overlaps poll)
        long gb = ((long)s*64 + b0+cb)*2048 + half*1024 + hu0 + cu;
        float xi=__ldg(gates+gb),     xf=__ldg(gates+gb+256);
        float xg=__ldg(gates+gb+512), xo=__ldg(gates+gb+768);
        bar_poll(ctr, tgt);
        // stage own-dir h: 2048 floats / 128 threads = 4 float4 each
        {
            const float* src = g_H + (((long)pp*2+half)*8+bg)*2048;
#pragma unroll
            for(int i=0;i<4;i++){
                float4 v = __ldcg((const float4*)(src + (ht + i*128)*4));
                *(float4*)&hsh[(ht + i*128)*4] = v;
            }
        }
        nbar(nb);
        // dot: own row r, k-half q, 8 batches
        {
            unsigned long long a0=0,a1=0,a2=0,a3=0;
#pragma unroll
            for(int j4=0;j4<32;j4++){
                float4 w4 = wreg[j4];
                const ulonglong2* hp = (const ulonglong2*)(hq + j4*32);
                ulonglong2 p0=hp[0],p1=hp[1],p2=hp[2],p3=hp[3];
                ulonglong2 p4=hp[4],p5=hp[5],p6=hp[6],p7=hp[7];
                unsigned long long w;
                w=pk2f(w4.x,w4.x); fma2(a0,w,p0.x);fma2(a1,w,p0.y);fma2(a2,w,p1.x);fma2(a3,w,p1.y);
                w=pk2f(w4.y,w4.y); fma2(a0,w,p2.x);fma2(a1,w,p2.y);fma2(a2,w,p3.x);fma2(a3,w,p3.y);
                w=pk2f(w4.z,w4.z); fma2(a0,w,p4.x);fma2(a1,w,p4.y);fma2(a2,w,p5.x);fma2(a3,w,p5.y);
                w=pk2f(w4.w,w4.w); fma2(a0,w,p6.x);fma2(a1,w,p6.y);fma2(a2,w,p7.x);fma2(a3,w,p7.y);
            }
            unsigned long long* pr = (unsigned long long*)&ps[(q*64+r)*PSP];
            pr[0]=a0; pr[1]=a1; pr[2]=a2; pr[3]=a3;
        }
        nbar(nb);
        // combine
        {
            #define RDQ(g) (ps[((g)*16+cu)*PSP+cb] + ps[(64+(g)*16+cu)*PSP+cb])
            float gi = RDQ(0)+xi, gf = RDQ(1)+xf, gg = RDQ(2)+xg, go = RDQ(3)+xo;
            c = sigm(gf)*c + sigm(gi)*tanhf(gg);
            float h = sigm(go)*tanhf(c);
            __stcg(&g_H[(((long)(1-pp)*2+half)*8+bg)*2048 + (hu0+cu)*8+cb], h);
            out[((long)s*64 + b0+cb)*512 + half*256 + hu0+cu] = h;
        }
        nbar(nb);
        if(ht==0) bar_arrive(ctr);
        tgt += 16;
    }
}

// ---------------- GCN banded adjacency ----------------
__global__ void k_band(const float* __restrict__ x, const float* __restrict__ mask,
                       float* __restrict__ o){
    int m = blockIdx.x; int s=m>>6, b=m&63;
    float mm = mask[b*512+s];
    float mn = (s<511)? mask[b*512+s+1] : 0.f;
    float mp = (s>0)?   mask[b*512+s-1] : 0.f;
    float rs = mm*(mp+mn)+1e-8f;
    float cn = mm*mn/rs, cp = mm*mp/rs;
    int t = threadIdx.x;
    float4 vn = (s<511)? ((const float4*)(x+((long)m+64)*256))[t] : make_float4(0,0,0,0);
    float4 vp = (s>0)?   ((const float4*)(x+((long)m-64)*256))[t] : make_float4(0,0,0,0);
    float4 r; r.x=cn*vn.x+cp*vp.x; r.y=cn*vn.y+cp*vp.y;
    r.z=cn*vn.z+cp*vp.z; r.w=cn*vn.w+cp*vp.w;
    ((float4*)(o+(long)m*256))[t]=r;
}

// ---------------- residual + LayerNorm + ReLU ----------------
__global__ void k_ln(const float* __restrict__ go, const float* __restrict__ xin,
                     const float* __restrict__ gamma, const float* __restrict__ beta,
                     float* __restrict__ o){
    __shared__ float rs1[8], rs2[8];
    long m = blockIdx.x; int t = threadIdx.x;
    float v = go[m*256+t] + xin[m*256+t];
    float s1=v, s2=v*v;
#pragma unroll
    for(int w=16;w;w>>=1){ s1+=__shfl_xor_sync(~0u,s1,w); s2+=__shfl_xor_sync(~0u,s2,w); }
    if((t&31)==0){ rs1[t>>5]=s1; rs2[t>>5]=s2; }
    __syncthreads();
    float S1=0,S2=0;
#pragma unroll
    for(int i=0;i<8;i++){ S1+=rs1[i]; S2+=rs2[i]; }
    float mu=S1*(1.f/256.f), var=S2*(1.f/256.f)-mu*mu;
    float inv=rsqrtf(var+1e-5f);
    float y=(v-mu)*inv*gamma[t]+beta[t];
    o[m*256+t]=fmaxf(y,0.f);
}

// ---------------- masked mean pooling + fuse ----------------
__global__ void k_pool(const float* __restrict__ lstm, const float* __restrict__ gcn,
                       const float* __restrict__ mask, const float* __restrict__ aux){
    int b = blockIdx.x, t = threadIdx.x;
    float dn=0.f;
    for(int s=0;s<512;s++) dn += mask[b*512+s];
    dn = fmaxf(dn,1e-8f);
    float acc=0.f;
    for(int s=0;s<512;s++) acc += lstm[((long)s*64+b)*512+t]*mask[b*512+s];
    g_FU[b*774+t]=acc/dn;
    if(t<256){
        float a2=0.f;
        for(int s=0;s<512;s++) a2 += gcn[((long)s*64+b)*256+t]*mask[b*512+s];
        g_FU[b*774+512+t]=a2/dn;
    }
    if(t<6) g_FU[b*774+768+t]=aux[b*6+t];
}

// ---------------- small FC ----------------
__global__ void k_fc(const float* __restrict__ in, const float* __restrict__ W,
                     const float* __restrict__ bias, float* __restrict__ o,
                     int K, int N, int relu){
    int idx = blockIdx.x*blockDim.x + threadIdx.x;
    if(idx >= 64*N) return;
    int b = idx/N, n = idx%N;
    const float* ip = in + (long)b*K;
    const float* wp = W + (long)n*K;
    float a=0.f;
    for(int k=0;k<K;k++) a += ip[k]*wp[k];
    a += bias[n];
    o[idx] = relu ? fmaxf(a,0.f) : a;
}

// ---------------- launch ----------------
extern "C" void kernel_launch(void* const* d_in, const int* in_sizes, int n_in,
                              void* d_out, int out_size){
    const int*   seq  = (const int*)  d_in[0];
    const float* mask = (const float*)d_in[1];
    const float* aux  = (const float*)d_in[2];
    const float* emb  = (const float*)d_in[3];
    const float* Wih0 = (const float*)d_in[4];
    const float* Whh0 = (const float*)d_in[5];
    const float* b0   = (const float*)d_in[6];
    const float* WihL = (const float*)d_in[7];
    const float* WhhL = (const float*)d_in[8];
    const float* bLp  = (const float*)d_in[9];
    const float* gW   = (const float*)d_in[10];
    const float* gb   = (const float*)d_in[11];
    const float* gga  = (const float*)d_in[12];
    const float* gbe  = (const float*)d_in[13];
    const float* f1W  = (const float*)d_in[14];
    const float* f1b  = (const float*)d_in[15];
    const float* f2W  = (const float*)d_in[16];
    const float* f2b  = (const float*)d_in[17];
    const float* h0W  = (const float*)d_in[18];
    const float* h0b  = (const float*)d_in[19];
    const float* h1W  = (const float*)d_in[20];
    const float* h1b  = (const float*)d_in[21];
    float* out = (float*)d_out;

    float *pEMB,*pXA,*pXB,*pGT,*pT0,*pT1,*pP0,*pP1,*pFU,*pS1,*pS2;
    __nv_bfloat16 *pA3,*pW3,*pW3G;
    cudaGetSymbolAddress((void**)&pEMB,g_EMB);
    cudaGetSymbolAddress((void**)&pXA, g_XA);
    cudaGetSymbolAddress((void**)&pXB, g_XB);
    cudaGetSymbolAddress((void**)&pGT, g_GT);
    cudaGetSymbolAddress((void**)&pT0, g_T0);
    cudaGetSymbolAddress((void**)&pT1, g_T1);
    cudaGetSymbolAddress((void**)&pP0, g_P0);
    cudaGetSymbolAddress((void**)&pP1, g_P1);
    cudaGetSymbolAddress((void**)&pFU, g_FU);
    cudaGetSymbolAddress((void**)&pS1, g_S1);
    cudaGetSymbolAddress((void**)&pS2, g_S2);
    cudaGetSymbolAddress((void**)&pA3, g_A3);
    cudaGetSymbolAddress((void**)&pW3, g_W3);
    cudaGetSymbolAddress((void**)&pW3G,g_W3G);
    cudaFuncSetAttribute(k_lstm, cudaFuncAttributeMaxDynamicSharedMemorySize, LSM);

    // k_lstm at launch index 3 (observed ncu capture slot)
    k_embsplit<<<32768,64>>>(seq, emb);                    // 0
    k_splitW<<<512,256>>>(Wih0, pW3, 256);                 // 1 (+ barrier reset)
    {   dim3 gg(2048/128, 32768/128);
        k_mma<<<gg,256>>>(pA3, pW3, b0, pGT, 768, 2048);   // 2
    }
    float* lo = pXA;
    k_lstm<<<128,256,LSM>>>(pGT, Whh0, Whh0 + 1024*256, lo);   // 3 <- ncu
    const float* inp = lo;
    for(int l=1;l<5;l++){
        const float* wih = WihL + (long)(l-1)*2*1024*512;
        const float* whh = WhhL + (long)(l-1)*2*1024*256;
        const float* bb  = bLp  + (long)(l-1)*2*1024;
        k_splitA<<<16384,256>>>(inp, pA3, 512);
        k_splitW<<<1024,256>>>(wih, pW3, 512);
        dim3 gg(2048/128, 32768/128);
        k_mma<<<gg,256>>>(pA3, pW3, bb, pGT, 1536, 2048);
        k_rst<<<1,512>>>();
        lo = (l&1) ? pXB : pXA;
        k_lstm<<<128,256,LSM>>>(pGT, whh, whh + 1024*256, lo);
        inp = lo;
    }
    const float* lstmOut = lo;

    k_splitW<<<64,256>>>(gW,             pW3G,            256);
    k_splitW<<<64,256>>>(gW + 256*256,   pW3G + 196608,   256);
    k_splitW<<<64,256>>>(gW + 2*256*256, pW3G + 2*196608, 256);

    const float* gin = pEMB;
    float* gout = pP0;
    for(int i=0;i<3;i++){
        k_band<<<32768,64>>>(gin, mask, pT0);
        k_splitA<<<8192,256>>>(pT0, pA3, 256);
        dim3 gg(256/128, 32768/128);
        k_mma<<<gg,256>>>(pA3, pW3G + (long)i*196608, gb + i*256, pT1, 768, 256);
        gout = (i&1) ? pP1 : pP0;
        k_ln<<<32768,256>>>(pT1, gin, gga + i*256, gbe + i*256, gout);
        gin = gout;
    }

    k_pool<<<64,512>>>(lstmOut, gout, mask, aux);
    k_fc<<<(64*512+255)/256,256>>>(pFU, f1W, f1b, pS1, 774, 512, 1);
    k_fc<<<(64*256+255)/256,256>>>(pS1, f2W, f2b, pS2, 512, 256, 1);
    k_fc<<<(64*10+255)/256,256>>>(pS2, h0W, h0b, out,      256, 10, 0);
    k_fc<<<(64*5 +255)/256,256>>>(pS2, h1W, h1b, out+640, 256,  5, 0);
}

// round 17
// speedup vs baseline: 1.6199x; 1.1453x over previous
#include <cuda_runtime.h>
#include <cuda_bf16.h>
#include <math.h>

// ---------------- static scratch ----------------
__device__ __align__(256) float g_EMB[512*64*256];
__device__ __align__(256) float g_XA [512*64*512];
__device__ __align__(256) float g_XB [512*64*512];
__device__ __align__(256) float g_GT [512*64*2048];
__device__ __align__(256) float g_T0 [512*64*256];
__device__ __align__(256) float g_T1 [512*64*256];
__device__ __align__(256) float g_P0 [512*64*256];
__device__ __align__(256) float g_P1 [512*64*256];
__device__ __align__(256) float g_H  [2*2*8*256*8];  // [pp][dir][bg][k][8b]
__device__ __align__(256) float g_FU [64*774];
__device__ __align__(256) float g_S1 [64*512];
__device__ __align__(256) float g_S2 [64*256];
__device__ __align__(256) __nv_bfloat16 g_A3 [32768L*1536];
__device__ __align__(256) __nv_bfloat16 g_W3 [2048L*1536];
__device__ __align__(256) __nv_bfloat16 g_W3G[3L*256*768];
__device__ unsigned g_barG[512];                     // 16 counters, 128B apart

// ---------------- helpers ----------------
__device__ __forceinline__ float sigm(float x){ return 1.f/(1.f+__expf(-x)); }
__device__ __forceinline__ void bar_arrive(unsigned* c){
    asm volatile("red.release.gpu.global.add.u32 [%0],1;"::"l"(c):"memory");
}
__device__ __forceinline__ void bar_poll(unsigned* c, unsigned tgt){
    unsigned v;
    while(1){
        asm volatile("ld.acquire.gpu.global.u32 %0,[%1];":"=r"(v):"l"(c):"memory");
        if(v>=tgt) break;
        __nanosleep(20);
    }
}
__device__ __forceinline__ ushort4 hi4(float4 v, float4& rem){
    __nv_bfloat16 h0=__float2bfloat16(v.x), h1=__float2bfloat16(v.y);
    __nv_bfloat16 h2=__float2bfloat16(v.z), h3=__float2bfloat16(v.w);
    rem.x = v.x-__bfloat162float(h0); rem.y = v.y-__bfloat162float(h1);
    rem.z = v.z-__bfloat162float(h2); rem.w = v.w-__bfloat162float(h3);
    return make_ushort4(__bfloat16_as_ushort(h0),__bfloat16_as_ushort(h1),
                        __bfloat16_as_ushort(h2),__bfloat16_as_ushort(h3));
}
__device__ __forceinline__ ushort4 bf4(float4 v){
    return make_ushort4(__bfloat16_as_ushort(__float2bfloat16(v.x)),
                        __bfloat16_as_ushort(__float2bfloat16(v.y)),
                        __bfloat16_as_ushort(__float2bfloat16(v.z)),
                        __bfloat16_as_ushort(__float2bfloat16(v.w)));
}

// ---------------- fused embedding gather + bf16 split (layer-1 A) ----------
__global__ void k_embsplit(const int* __restrict__ seq, const float* __restrict__ tab){
    int m = blockIdx.x; int s = m>>6, b = m&63;
    long tok = seq[b*512+s];
    int t = threadIdx.x;
    float4 v = ((const float4*)(tab + tok*256))[t];
    ((float4*)(g_EMB + (long)m*256))[t] = v;
    float4 r; ushort4 hh = hi4(v, r); ushort4 ll = bf4(r);
    unsigned short* yp = (unsigned short*)(g_A3 + (long)m*768 + t*4);
    *(ushort4*)yp = hh;
    *(ushort4*)(yp + 256) = hh;
    *(ushort4*)(yp + 512) = ll;
}

__global__ void k_rst(){ g_barG[threadIdx.x] = 0u; }

// ---------------- bf16 split conversions ----------------
__global__ void k_splitA(const float* __restrict__ X, __nv_bfloat16* __restrict__ Y, int K){
    long idx = (long)blockIdx.x*256 + threadIdx.x;
    int kq = K>>2;
    long m = idx/kq; int k4 = (int)(idx - m*kq)*4;
    float4 v = *(const float4*)(X + m*K + k4);
    float4 r; ushort4 hh = hi4(v, r); ushort4 ll = bf4(r);
    unsigned short* yp = (unsigned short*)(Y + m*3L*K + k4);
    *(ushort4*)yp = hh;
    *(ushort4*)(yp + K) = hh;
    *(ushort4*)(yp + 2*K) = ll;
}
__global__ void k_splitW(const float* __restrict__ X, __nv_bfloat16* __restrict__ Y, int K){
    if(blockIdx.x==0){
        g_barG[threadIdx.x] = 0u;
        g_barG[256+threadIdx.x] = 0u;
    }
    long idx = (long)blockIdx.x*256 + threadIdx.x;
    int kq = K>>2;
    long m = idx/kq; int k4 = (int)(idx - m*kq)*4;
    float4 v = *(const float4*)(X + m*K + k4);
    float4 r; ushort4 hh = hi4(v, r); ushort4 ll = bf4(r);
    unsigned short* yp = (unsigned short*)(Y + m*3L*K + k4);
    *(ushort4*)yp = hh;
    *(ushort4*)(yp + K) = ll;
    *(ushort4*)(yp + 2*K) = hh;
}

// ---------------- tensor-core GEMM (unchanged) ----------------
#define SPAD 72
__global__ void __launch_bounds__(256,2) k_mma(const __nv_bfloat16* __restrict__ A,
        const __nv_bfloat16* __restrict__ W, const float* __restrict__ bias,
        float* __restrict__ C, int Ks, int N){
    __shared__ __align__(16) __nv_bfloat16 As[128*SPAD];
    __shared__ __align__(16) __nv_bfloat16 Bs[128*SPAD];
    int tid = threadIdx.x;
    int m0 = blockIdx.y*128, n0 = blockIdx.x*128;
    int warp = tid>>5, lane = tid&31;
    int wm = (warp>>1)*32, wn = (warp&1)*64;
    int gid = lane>>2, tig = lane&3;
    float acc[2][8][4];
#pragma unroll
    for(int i=0;i<2;i++)
#pragma unroll
        for(int j=0;j<8;j++){ acc[i][j][0]=0.f; acc[i][j][1]=0.f; acc[i][j][2]=0.f; acc[i][j][3]=0.f; }
    for(int kt=0; kt<Ks; kt+=64){
#pragma unroll
        for(int i=0;i<4;i++){
            int idx = i*256 + tid;
            int r = idx>>3, c = (idx&7)*8;
            *(float4*)&As[r*SPAD + c] = *(const float4*)(A + (long)(m0+r)*Ks + kt + c);
            *(float4*)&Bs[r*SPAD + c] = *(const float4*)(W + (long)(n0+r)*Ks + kt + c);
        }
        __syncthreads();
#pragma unroll
        for(int kk=0;kk<4;kk++){
            unsigned a[2][4];
#pragma unroll
            for(int mt=0;mt<2;mt++){
                const __nv_bfloat16* ab = &As[(wm+mt*16+gid)*SPAD + kk*16 + tig*2];
                a[mt][0] = *(const unsigned*)ab;
                a[mt][1] = *(const unsigned*)(ab + 8*SPAD);
                a[mt][2] = *(const unsigned*)(ab + 8);
                a[mt][3] = *(const unsigned*)(ab + 8*SPAD + 8);
            }
#pragma unroll
            for(int nt=0;nt<8;nt++){
                const __nv_bfloat16* bb = &Bs[(wn+nt*8+gid)*SPAD + kk*16 + tig*2];
                unsigned b0 = *(const unsigned*)bb;
                unsigned b1 = *(const unsigned*)(bb + 8);
#pragma unroll
                for(int mt=0;mt<2;mt++){
                    asm volatile(
                        "mma.sync.aligned.m16n8k16.row.col.f32.bf16.bf16.f32 "
                        "{%0,%1,%2,%3},{%4,%5,%6,%7},{%8,%9},{%0,%1,%2,%3};\n"
                        : "+f"(acc[mt][nt][0]), "+f"(acc[mt][nt][1]),
                          "+f"(acc[mt][nt][2]), "+f"(acc[mt][nt][3])
                        : "r"(a[mt][0]), "r"(a[mt][1]), "r"(a[mt][2]), "r"(a[mt][3]),
                          "r"(b0), "r"(b1));
                }
            }
        }
        __syncthreads();
    }
#pragma unroll
    for(int mt=0;mt<2;mt++){
#pragma unroll
        for(int nt=0;nt<8;nt++){
            int row = m0 + wm + mt*16 + gid;
            int col = n0 + wn + nt*8 + tig*2;
            float b0v = bias[col], b1v = bias[col+1];
            *(float2*)&C[(long)row*N + col] =
                make_float2(acc[mt][nt][0]+b0v, acc[mt][nt][1]+b1v);
            *(float2*)&C[(long)(row+8)*N + col] =
                make_float2(acc[mt][nt][2]+b0v, acc[mt][nt][3]+b1v);
        }
    }
}

// ---------------- persistent LSTM: tensor-core recurrent dot ----------------
// 256 CTAs = dir(2) x bg(8 of 8b) x hb(16 of 16u); 2 CTAs/SM. Per step:
// poll | stage h + hi/lo bf16 split | 3-pass mma (hi.hi + hi.lo + lo.hi),
// M=16(8 batch), N=8/warp, K=256 | combine | arrive. Whh hi/lo in smem.
#define KST 264
#define LSM ((2*64*KST + 2*8*KST)*2 + 64*8*4)

__global__ void __launch_bounds__(256) k_lstm(const float* __restrict__ gates,
        const float* __restrict__ WhhA, const float* __restrict__ WhhB,
        float* __restrict__ out){
    extern __shared__ char smraw[];
    __nv_bfloat16* Wh = (__nv_bfloat16*)smraw;       // [2 sel][64 row][KST]
    __nv_bfloat16* hs = Wh + 2*64*KST;               // [2 sel][8 b][KST]
    float* ps = (float*)(hs + 2*8*KST);              // [64 row][8 b]
    int tid = threadIdx.x, bid = blockIdx.x;
    int dir = bid>>7, bg = (bid>>4)&7, hb = bid&15;
    int hu0 = hb*16, b0 = bg*8;
    const float* Whh = dir ? WhhB : WhhA;
    // load + split Whh slice (64 rows x 256 k) into smem hi/lo
    for(int i=tid;i<4096;i+=256){
        int row = i>>6, c4 = (i&63)*4;
        int g = row>>4, u = row&15;
        float4 v = *(const float4*)(Whh + (long)(g*256+hu0+u)*256 + c4);
        float4 r; ushort4 hh = hi4(v, r); ushort4 ll = bf4(r);
        *(ushort4*)&Wh[row*KST + c4] = hh;
        *(ushort4*)&Wh[64*KST + row*KST + c4] = ll;
    }
    int lane = tid&31, warp = tid>>5;
    int gid = lane>>2, tig = lane&3;
    int cu = tid>>3, cb = tid&7;     // combine (t<128) & conv mapping
    unsigned* ctr = &g_barG[(dir*8+bg)*32];
    float c = 0.f;
    if(tid<128) g_H[(((long)0*2+dir)*8+bg)*2048 + (hu0+cu)*8+cb] = 0.f;
    __syncthreads();
    if(tid==0) bar_arrive(ctr);
    unsigned tgt = 16;
    const __nv_bfloat16* Bs0 = Wh + (warp*8+gid)*KST + tig*2;
    const __nv_bfloat16* As0 = hs + gid*KST + tig*2;
    for(int si=0; si<512; si++){
        int s = dir ? 511-si : si;
        int pp = si&1;
        // gate prefetch (immutable; overlaps poll)
        float xi,xf,xg,xo;
        if(tid<128){
            long gb = ((long)s*64 + b0+cb)*2048 + dir*1024 + hu0 + cu;
            xi=__ldg(gates+gb);     xf=__ldg(gates+gb+256);
            xg=__ldg(gates+gb+512); xo=__ldg(gates+gb+768);
        }
        bar_poll(ctr, tgt);
        // stage h + hi/lo split: thread (b=cb, kg=cu 0..31 of 8 k)
        {
            const float* src = g_H + (((long)pp*2+dir)*8+bg)*2048 + cb;
            float4 v0, v1;
            v0.x=__ldcg(src+(cu*8+0)*8); v0.y=__ldcg(src+(cu*8+1)*8);
            v0.z=__ldcg(src+(cu*8+2)*8); v0.w=__ldcg(src+(cu*8+3)*8);
            v1.x=__ldcg(src+(cu*8+4)*8); v1.y=__ldcg(src+(cu*8+5)*8);
            v1.z=__ldcg(src+(cu*8+6)*8); v1.w=__ldcg(src+(cu*8+7)*8);
            float4 r0, r1;
            ushort4 h0 = hi4(v0, r0), h1 = hi4(v1, r1);
            ushort4 l0 = bf4(r0),     l1 = bf4(r1);
            ushort4* dh = (ushort4*)&hs[cb*KST + cu*8];
            dh[0] = h0; dh[1] = h1;
            ushort4* dl = (ushort4*)&hs[8*KST + cb*KST + cu*8];
            dl[0] = l0; dl[1] = l1;
        }
        __syncthreads();
        // 3-pass mma: (A=hi,B=hi), (A=hi,B=lo), (A=lo,B=hi)
        float c0=0.f, c1=0.f, c2=0.f, c3=0.f;
#pragma unroll
        for(int pass=0; pass<3; pass++){
            const __nv_bfloat16* As = As0 + (pass==2 ? 8*KST : 0);
            const __nv_bfloat16* Bs = Bs0 + (pass==1 ? 64*KST : 0);
#pragma unroll
            for(int kt=0; kt<16; kt++){
                unsigned a0 = *(const unsigned*)(As + kt*16);
                unsigned a2 = *(const unsigned*)(As + kt*16 + 8);
                unsigned bb0 = *(const unsigned*)(Bs + kt*16);
                unsigned bb1 = *(const unsigned*)(Bs + kt*16 + 8);
                asm volatile(
                    "mma.sync.aligned.m16n8k16.row.col.f32.bf16.bf16.f32 "
                    "{%0,%1,%2,%3},{%4,%5,%6,%7},{%8,%9},{%0,%1,%2,%3};\n"
                    : "+f"(c0),"+f"(c1),"+f"(c2),"+f"(c3)
                    : "r"(a0),"r"(0u),"r"(a2),"r"(0u),"r"(bb0),"r"(bb1));
            }
        }
        // epilogue: c0,c1 = (batch=gid, row=warp*8+tig*2(+1)); c2,c3 padding
        ps[(warp*8+tig*2)*8 + gid]   = c0;
        ps[(warp*8+tig*2+1)*8 + gid] = c1;
        __syncthreads();
        if(tid<128){
            float gi = ps[(     cu)*8+cb] + xi;
            float gf = ps[(16+cu)*8+cb] + xf;
            float gg = ps[(32+cu)*8+cb] + xg;
            float go = ps[(48+cu)*8+cb] + xo;
            c = sigm(gf)*c + sigm(gi)*tanhf(gg);
            float h = sigm(go)*tanhf(c);
            __stcg(&g_H[(((long)(1-pp)*2+dir)*8+bg)*2048 + (hu0+cu)*8+cb], h);
            out[((long)s*64 + b0+cb)*512 + dir*256 + hu0+cu] = h;
        }
        __syncthreads();
        if(tid==0) bar_arrive(ctr);
        tgt += 16;
    }
}

// ---------------- GCN banded adjacency ----------------
__global__ void k_band(const float* __restrict__ x, const float* __restrict__ mask,
                       float* __restrict__ o){
    int m = blockIdx.x; int s=m>>6, b=m&63;
    float mm = mask[b*512+s];
    float mn = (s<511)? mask[b*512+s+1] : 0.f;
    float mp = (s>0)?   mask[b*512+s-1] : 0.f;
    float rs = mm*(mp+mn)+1e-8f;
    float cn = mm*mn/rs, cp = mm*mp/rs;
    int t = threadIdx.x;
    float4 vn = (s<511)? ((const float4*)(x+((long)m+64)*256))[t] : make_float4(0,0,0,0);
    float4 vp = (s>0)?   ((const float4*)(x+((long)m-64)*256))[t] : make_float4(0,0,0,0);
    float4 r; r.x=cn*vn.x+cp*vp.x; r.y=cn*vn.y+cp*vp.y;
    r.z=cn*vn.z+cp*vp.z; r.w=cn*vn.w+cp*vp.w;
    ((float4*)(o+(long)m*256))[t]=r;
}

// ---------------- residual + LayerNorm + ReLU ----------------
__global__ void k_ln(const float* __restrict__ go, const float* __restrict__ xin,
                     const float* __restrict__ gamma, const float* __restrict__ beta,
                     float* __restrict__ o){
    __shared__ float rs1[8], rs2[8];
    long m = blockIdx.x; int t = threadIdx.x;
    float v = go[m*256+t] + xin[m*256+t];
    float s1=v, s2=v*v;
#pragma unroll
    for(int w=16;w;w>>=1){ s1+=__shfl_xor_sync(~0u,s1,w); s2+=__shfl_xor_sync(~0u,s2,w); }
    if((t&31)==0){ rs1[t>>5]=s1; rs2[t>>5]=s2; }
    __syncthreads();
    float S1=0,S2=0;
#pragma unroll
    for(int i=0;i<8;i++){ S1+=rs1[i]; S2+=rs2[i]; }
    float mu=S1*(1.f/256.f), var=S2*(1.f/256.f)-mu*mu;
    float inv=rsqrtf(var+1e-5f);
    float y=(v-mu)*inv*gamma[t]+beta[t];
    o[m*256+t]=fmaxf(y,0.f);
}

// ---------------- masked mean pooling + fuse ----------------
__global__ void k_pool(const float* __restrict__ lstm, const float* __restrict__ gcn,
                       const float* __restrict__ mask, const float* __restrict__ aux){
    int b = blockIdx.x, t = threadIdx.x;
    float dn=0.f;
    for(int s=0;s<512;s++) dn += mask[b*512+s];
    dn = fmaxf(dn,1e-8f);
    float acc=0.f;
    for(int s=0;s<512;s++) acc += lstm[((long)s*64+b)*512+t]*mask[b*512+s];
    g_FU[b*774+t]=acc/dn;
    if(t<256){
        float a2=0.f;
        for(int s=0;s<512;s++) a2 += gcn[((long)s*64+b)*256+t]*mask[b*512+s];
        g_FU[b*774+512+t]=a2/dn;
    }
    if(t<6) g_FU[b*774+768+t]=aux[b*6+t];
}

// ---------------- small FC ----------------
__global__ void k_fc(const float* __restrict__ in, const float* __restrict__ W,
                     const float* __restrict__ bias, float* __restrict__ o,
                     int K, int N, int relu){
    int idx = blockIdx.x*blockDim.x + threadIdx.x;
    if(idx >= 64*N) return;
    int b = idx/N, n = idx%N;
    const float* ip = in + (long)b*K;
    const float* wp = W + (long)n*K;
    float a=0.f;
    for(int k=0;k<K;k++) a += ip[k]*wp[k];
    a += bias[n];
    o[idx] = relu ? fmaxf(a,0.f) : a;
}

// ---------------- launch ----------------
extern "C" void kernel_launch(void* const* d_in, const int* in_sizes, int n_in,
                              void* d_out, int out_size){
    const int*   seq  = (const int*)  d_in[0];
    const float* mask = (const float*)d_in[1];
    const float* aux  = (const float*)d_in[2];
    const float* emb  = (const float*)d_in[3];
    const float* Wih0 = (const float*)d_in[4];
    const float* Whh0 = (const float*)d_in[5];
    const float* b0   = (const float*)d_in[6];
    const float* WihL = (const float*)d_in[7];
    const float* WhhL = (const float*)d_in[8];
    const float* bLp  = (const float*)d_in[9];
    const float* gW   = (const float*)d_in[10];
    const float* gb   = (const float*)d_in[11];
    const float* gga  = (const float*)d_in[12];
    const float* gbe  = (const float*)d_in[13];
    const float* f1W  = (const float*)d_in[14];
    const float* f1b  = (const float*)d_in[15];
    const float* f2W  = (const float*)d_in[16];
    const float* f2b  = (const float*)d_in[17];
    const float* h0W  = (const float*)d_in[18];
    const float* h0b  = (const float*)d_in[19];
    const float* h1W  = (const float*)d_in[20];
    const float* h1b  = (const float*)d_in[21];
    float* out = (float*)d_out;

    float *pEMB,*pXA,*pXB,*pGT,*pT0,*pT1,*pP0,*pP1,*pFU,*pS1,*pS2;
    __nv_bfloat16 *pA3,*pW3,*pW3G;
    cudaGetSymbolAddress((void**)&pEMB,g_EMB);
    cudaGetSymbolAddress((void**)&pXA, g_XA);
    cudaGetSymbolAddress((void**)&pXB, g_XB);
    cudaGetSymbolAddress((void**)&pGT, g_GT);
    cudaGetSymbolAddress((void**)&pT0, g_T0);
    cudaGetSymbolAddress((void**)&pT1, g_T1);
    cudaGetSymbolAddress((void**)&pP0, g_P0);
    cudaGetSymbolAddress((void**)&pP1, g_P1);
    cudaGetSymbolAddress((void**)&pFU, g_FU);
    cudaGetSymbolAddress((void**)&pS1, g_S1);
    cudaGetSymbolAddress((void**)&pS2, g_S2);
    cudaGetSymbolAddress((void**)&pA3, g_A3);
    cudaGetSymbolAddress((void**)&pW3, g_W3);
    cudaGetSymbolAddress((void**)&pW3G,g_W3G);
    cudaFuncSetAttribute(k_lstm, cudaFuncAttributeMaxDynamicSharedMemorySize, LSM);

    // k_lstm at launch index 3 (observed ncu capture slot)
    k_embsplit<<<32768,64>>>(seq, emb);                    // 0
    k_splitW<<<512,256>>>(Wih0, pW3, 256);                 // 1 (+ barrier reset)
    {   dim3 gg(2048/128, 32768/128);
        k_mma<<<gg,256>>>(pA3, pW3, b0, pGT, 768, 2048);   // 2
    }
    float* lo = pXA;
    k_lstm<<<256,256,LSM>>>(pGT, Whh0, Whh0 + 1024*256, lo);   // 3 <- ncu
    const float* inp = lo;
    for(int l=1;l<5;l++){
        const float* wih = WihL + (long)(l-1)*2*1024*512;
        const float* whh = WhhL + (long)(l-1)*2*1024*256;
        const float* bb  = bLp  + (long)(l-1)*2*1024;
        k_splitA<<<16384,256>>>(inp, pA3, 512);
        k_splitW<<<1024,256>>>(wih, pW3, 512);
        dim3 gg(2048/128, 32768/128);
        k_mma<<<gg,256>>>(pA3, pW3, bb, pGT, 1536, 2048);
        k_rst<<<1,512>>>();
        lo = (l&1) ? pXB : pXA;
        k_lstm<<<256,256,LSM>>>(pGT, whh, whh + 1024*256, lo);
        inp = lo;
    }
    const float* lstmOut = lo;

    k_splitW<<<64,256>>>(gW,             pW3G,            256);
    k_splitW<<<64,256>>>(gW + 256*256,   pW3G + 196608,   256);
    k_splitW<<<64,256>>>(gW + 2*256*256, pW3G + 2*196608, 256);

    const float* gin = pEMB;
    float* gout = pP0;
    for(int i=0;i<3;i++){
        k_band<<<32768,64>>>(gin, mask, pT0);
        k_splitA<<<8192,256>>>(pT0, pA3, 256);
        dim3 gg(256/128, 32768/128);
        k_mma<<<gg,256>>>(pA3, pW3G + (long)i*196608, gb + i*256, pT1, 768, 256);
        gout = (i&1) ? pP1 : pP0;
        k_ln<<<32768,256>>>(pT1, gin, gga + i*256, gbe + i*256, gout);
        gin = gout;
    }

    k_pool<<<64,512>>>(lstmOut, gout, mask, aux);
    k_fc<<<(64*512+255)/256,256>>>(pFU, f1W, f1b, pS1, 774, 512, 1);
    k_fc<<<(64*256+255)/256,256>>>(pS1, f2W, f2b, pS2, 512, 256, 1);
    k_fc<<<(64*10+255)/256,256>>>(pS2, h0W, h0b, out,      256, 10, 0);
    k_fc<<<(64*5 +255)/256,256>>>(pS2, h1W, h1b, out+640, 256,  5, 0);
}